// round 7
// baseline (speedup 1.0000x reference)
#include <cuda_runtime.h>
#include <cuda_bf16.h>
#include <cstdint>

// Problem constants
#define BB 16
#define RR 1024
#define TT 512
#define DD 1024
#define HH 1024

typedef __nv_bfloat16 bf16;

// ---------------- scratch (__device__ globals; no allocation allowed) -------
__device__ float g_P [BB * RR * 2 * TT];      // 64 MB (also reused early as M split-K partials)
__device__ bf16  g_Xh[BB * RR * DD], g_Xl[BB * RR * DD];
__device__ bf16  g_Yh[BB * TT * DD], g_Yl[BB * TT * DD];
__device__ bf16  g_Wrh[DD * HH], g_Wrl[DD * HH];
__device__ bf16  g_Wqh[DD * HH], g_Wql[DD * HH];
__device__ bf16  g_Mh[DD * DD], g_Ml[DD * DD];
__device__ bf16  g_W2h[BB * 2 * TT * DD], g_W2l[BB * 2 * TT * DD];
__device__ float g_c[BB * TT], g_z[BB * TT], g_base[BB * RR];
__device__ float g_wc[DD];

// ---------------- helpers ---------------------------------------------------
__device__ __forceinline__ uint32_t smem_u32(const void* p) {
    return (uint32_t)__cvta_generic_to_shared(p);
}
__device__ __forceinline__ void cp16(void* s, const void* g) {
    asm volatile("cp.async.ca.shared.global [%0], [%1], 16;\n"
                 :: "r"(smem_u32(s)), "l"(g));
}
__device__ __forceinline__ void cp_commit() { asm volatile("cp.async.commit_group;\n"); }
template <int N>
__device__ __forceinline__ void cp_wait() { asm volatile("cp.async.wait_group %0;\n" :: "n"(N)); }

__device__ __forceinline__ void ldm_x4(uint32_t* r, uint32_t addr) {
    asm volatile("ldmatrix.sync.aligned.m8n8.x4.shared.b16 {%0,%1,%2,%3}, [%4];"
                 : "=r"(r[0]), "=r"(r[1]), "=r"(r[2]), "=r"(r[3]) : "r"(addr));
}
__device__ __forceinline__ void mma16816(float* d, const uint32_t* a, const uint32_t* b) {
    asm volatile(
        "mma.sync.aligned.m16n8k16.row.col.f32.bf16.bf16.f32 "
        "{%0,%1,%2,%3},{%4,%5,%6,%7},{%8,%9},{%0,%1,%2,%3};"
        : "+f"(d[0]), "+f"(d[1]), "+f"(d[2]), "+f"(d[3])
        : "r"(a[0]), "r"(a[1]), "r"(a[2]), "r"(a[3]), "r"(b[0]), "r"(b[1]));
}

__device__ __forceinline__ void split1(float v, bf16& h, bf16& l) {
    h = __float2bfloat16(v);
    l = __float2bfloat16(v - __bfloat162float(h));
}
__device__ __forceinline__ uint32_t pk2(bf16 a, bf16 b) {
    return (uint32_t)__bfloat16_as_ushort(a) | ((uint32_t)__bfloat16_as_ushort(b) << 16);
}

// ---------------- split kernels ---------------------------------------------
__global__ __launch_bounds__(256) void split_kernel(
    const float4* __restrict__ in, uint2* __restrict__ h, uint2* __restrict__ l)
{
    int i = blockIdx.x * 256 + threadIdx.x;
    float4 v = in[i];
    bf16 h0, l0, h1, l1, h2, l2, h3, l3;
    split1(v.x, h0, l0); split1(v.y, h1, l1); split1(v.z, h2, l2); split1(v.w, h3, l3);
    h[i] = make_uint2(pk2(h0, h1), pk2(h2, h3));
    l[i] = make_uint2(pk2(l0, l1), pk2(l2, l3));
}

// W2 bottom half: split(Y[b,t,d] * ws3[d]) -> W2h/W2l rows [512,1024)
__global__ __launch_bounds__(256) void yw_split_kernel(
    const float4* __restrict__ Y, const float4* __restrict__ ws3,
    uint2* __restrict__ W2h, uint2* __restrict__ W2l)
{
    int idx4 = blockIdx.x * 256 + threadIdx.x;   // [0, 16*512*1024/4)
    int d4 = idx4 & 255;
    int b  = idx4 >> 17;
    float4 y = Y[idx4];
    float4 w = ws3[d4];
    bf16 h0,l0,h1,l1,h2,l2,h3,l3;
    split1(y.x * w.x, h0, l0); split1(y.y * w.y, h1, l1);
    split1(y.z * w.z, h2, l2); split1(y.w * w.w, h3, l3);
    int o = idx4 + (b + 1) * 131072;
    W2h[o] = make_uint2(pk2(h0, h1), pk2(h2, h3));
    W2l[o] = make_uint2(pk2(l0, l1), pk2(l2, l3));
}

// reduce 4 split-K fp32 partials of M and split to bf16 h/l
__global__ __launch_bounds__(256) void reduce_split_kernel(
    const float4* __restrict__ part, uint2* __restrict__ h, uint2* __restrict__ l)
{
    int i = blockIdx.x * 256 + threadIdx.x;      // [0, 1024*1024/4)
    const int S = DD * DD / 4;
    float4 a = part[i], b = part[i + S], c = part[i + 2 * S], d = part[i + 3 * S];
    float4 v = make_float4(a.x + b.x + c.x + d.x, a.y + b.y + c.y + d.y,
                           a.z + b.z + c.z + d.z, a.w + b.w + c.w + d.w);
    bf16 h0, l0, h1, l1, h2, l2, h3, l3;
    split1(v.x, h0, l0); split1(v.y, h1, l1); split1(v.z, h2, l2); split1(v.w, h3, l3);
    h[i] = make_uint2(pk2(h0, h1), pk2(h2, h3));
    l[i] = make_uint2(pk2(l0, l1), pk2(l2, l3));
}

// ---------------- bf16 split NT GEMM (mma.sync) ------------------------------
// C[m,n] = sum over phases of (Ah|Al)[m,k]*(Bh|Bl)[n,k]; phases: hh, lh, hl.
// Blocks with n0 >= nlim3 run only 2 phases (hh, lh).
// Per phase, k covers [koff, koff+Kp). Row stride of A/B is fixed at 1024 (=LD).
// EPI=0: fp32 store. EPI=1: split-store bf16 into Ch/Cl.
#define LD 1024
template <int EPI>
__global__ __launch_bounds__(256, 2) void gemm_bf16_nt(
    const bf16* __restrict__ Ah, const bf16* __restrict__ Al,
    const bf16* __restrict__ Bh, const bf16* __restrict__ Bl,
    float* __restrict__ C, bf16* __restrict__ Ch, bf16* __restrict__ Cl,
    int ldc, long long sA, long long sB, long long sC,
    int Kp, int koffmul, int nlim3)
{
    const int bz = blockIdx.z;
    Ah += bz * sA; Al += bz * sA; Bh += bz * sB; Bl += bz * sB;
    const int koff = bz * koffmul;

    const int m0 = blockIdx.y * 128, n0 = blockIdx.x * 128;
    const int tid = threadIdx.x, lane = tid & 31, wid = tid >> 5;
    const int wm = (wid & 1) * 64, wn = (wid >> 1) * 32;

    __shared__ bf16 sm[2][2][128 * 40];

    float acc[4][4][4];
    #pragma unroll
    for (int i = 0; i < 4; i++)
        #pragma unroll
        for (int j = 0; j < 4; j++)
            #pragma unroll
            for (int q = 0; q < 4; q++) acc[i][j][q] = 0.f;

    const int ar0 = tid >> 2,          ak0 = (tid & 3) * 8;
    const int ar1 = (tid + 256) >> 2,  ak1 = ((tid + 256) & 3) * 8;

    const int nph = (n0 < nlim3) ? 3 : 2;
    const int nch = nph * Kp / 32;

    auto issue = [&](int chunk, int stage) {
        int kk = chunk * 32;
        int phase = kk / Kp, kin = koff + kk - phase * Kp;
        const bf16* pA = (phase == 1) ? Al : Ah;
        const bf16* pB = (phase == 2) ? Bl : Bh;
        cp16(&sm[stage][0][ar0 * 40 + ak0], pA + (long long)(m0 + ar0) * LD + kin + ak0);
        cp16(&sm[stage][0][ar1 * 40 + ak1], pA + (long long)(m0 + ar1) * LD + kin + ak1);
        cp16(&sm[stage][1][ar0 * 40 + ak0], pB + (long long)(n0 + ar0) * LD + kin + ak0);
        cp16(&sm[stage][1][ar1 * 40 + ak1], pB + (long long)(n0 + ar1) * LD + kin + ak1);
        cp_commit();
    };

    issue(0, 0);

    const int aRow = lane & 15, aKof = (lane >> 4) * 8;
    const int bRow = ((lane >> 4) << 3) + (lane & 7), bKof = ((lane >> 3) & 1) * 8;

    for (int c = 0; c < nch; c++) {
        int st = c & 1;
        if (c + 1 < nch) { issue(c + 1, st ^ 1); cp_wait<1>(); }
        else             { cp_wait<0>(); }
        __syncthreads();

        #pragma unroll
        for (int ks = 0; ks < 32; ks += 16) {
            uint32_t af[4][4];
            #pragma unroll
            for (int mt = 0; mt < 4; mt++)
                ldm_x4(af[mt], smem_u32(&sm[st][0][(wm + mt * 16 + aRow) * 40 + ks + aKof]));
            uint32_t bfr[2][4];
            #pragma unroll
            for (int bt = 0; bt < 2; bt++)
                ldm_x4(bfr[bt], smem_u32(&sm[st][1][(wn + bt * 16 + bRow) * 40 + ks + bKof]));
            #pragma unroll
            for (int mt = 0; mt < 4; mt++) {
                #pragma unroll
                for (int nt = 0; nt < 4; nt++) {
                    mma16816(acc[mt][nt], af[mt], &bfr[nt >> 1][(nt & 1) * 2]);
                }
            }
        }
        __syncthreads();
    }

    // epilogue
    const int tg = lane >> 2, tl = lane & 3;
    #pragma unroll
    for (int mt = 0; mt < 4; mt++) {
        #pragma unroll
        for (int nt = 0; nt < 4; nt++) {
            int m = m0 + wm + mt * 16 + tg;
            int n = n0 + wn + nt * 8 + 2 * tl;
            float v0 = acc[mt][nt][0], v1 = acc[mt][nt][1];
            float v2 = acc[mt][nt][2], v3 = acc[mt][nt][3];
            if (EPI == 0) {
                float* Cb = C + bz * sC;
                *reinterpret_cast<float2*>(&Cb[(long long)m * ldc + n])       = make_float2(v0, v1);
                *reinterpret_cast<float2*>(&Cb[(long long)(m + 8) * ldc + n]) = make_float2(v2, v3);
            } else {
                bf16 h0,l0,h1,l1,h2,l2,h3,l3;
                split1(v0, h0, l0); split1(v1, h1, l1); split1(v2, h2, l2); split1(v3, h3, l3);
                bf16* Hb = Ch + bz * sC; bf16* Lb = Cl + bz * sC;
                *reinterpret_cast<uint32_t*>(&Hb[(long long)m * ldc + n])       = pk2(h0, h1);
                *reinterpret_cast<uint32_t*>(&Lb[(long long)m * ldc + n])       = pk2(l0, l1);
                *reinterpret_cast<uint32_t*>(&Hb[(long long)(m + 8) * ldc + n]) = pk2(h2, h3);
                *reinterpret_cast<uint32_t*>(&Lb[(long long)(m + 8) * ldc + n]) = pk2(l2, l3);
            }
        }
    }
}

// ---------------- aux kernels (fp32) ----------------------------------------
__global__ __launch_bounds__(256) void rowdot_kernel(
    const float* __restrict__ A, const float* __restrict__ v,
    const float* __restrict__ addp, float* __restrict__ out, int K)
{
    int row = blockIdx.x * 8 + (threadIdx.x >> 5);
    int lane = threadIdx.x & 31;
    const float* a = A + (long long)row * K;
    float s = 0.f;
    for (int i = lane * 4; i < K; i += 128) {
        float4 x = *reinterpret_cast<const float4*>(&a[i]);
        float4 w = *reinterpret_cast<const float4*>(&v[i]);
        s += x.x * w.x + x.y * w.y + x.z * w.z + x.w * w.w;
    }
    #pragma unroll
    for (int o = 16; o; o >>= 1) s += __shfl_xor_sync(0xffffffffu, s, o);
    if (lane == 0) out[row] = s + (addp ? addp[0] : 0.f);
}

// c[row] = Y[row]·wc ; z[row] = Y[row]·w2
__global__ __launch_bounds__(256) void rowdot2_kernel(
    const float* __restrict__ Y, const float* __restrict__ wc,
    const float* __restrict__ w2, float* __restrict__ cb, float* __restrict__ zb)
{
    int row = blockIdx.x * 8 + (threadIdx.x >> 5);
    int lane = threadIdx.x & 31;
    const float* a = Y + (long long)row * DD;
    float s1 = 0.f, s2 = 0.f;
    for (int i = lane * 4; i < DD; i += 128) {
        float4 x = *reinterpret_cast<const float4*>(&a[i]);
        float4 u = *reinterpret_cast<const float4*>(&wc[i]);
        float4 v = *reinterpret_cast<const float4*>(&w2[i]);
        s1 += x.x * u.x + x.y * u.y + x.z * u.z + x.w * u.w;
        s2 += x.x * v.x + x.y * v.y + x.z * v.z + x.w * v.w;
    }
    #pragma unroll
    for (int o = 16; o; o >>= 1) {
        s1 += __shfl_xor_sync(0xffffffffu, s1, o);
        s2 += __shfl_xor_sync(0xffffffffu, s2, o);
    }
    if (lane == 0) { cb[row] = s1; zb[row] = s2; }
}

__global__ __launch_bounds__(256) void softmax_out_kernel(
    const float* __restrict__ P, const float* __restrict__ c,
    const float* __restrict__ z, const float* __restrict__ base,
    float* __restrict__ out)
{
    const int b = blockIdx.y, r = blockIdx.x;
    const float* Prow = P + ((long long)b * RR + r) * (2 * TT);
    const float* cbp = c + b * TT;
    const float* zbp = z + b * TT;
    const int t = threadIdx.x;
    const int lane = t & 31, wid = t >> 5;

    float s0 = Prow[t]       + cbp[t];
    float s1 = Prow[t + 256] + cbp[t + 256];
    float g0 = Prow[512 + t];
    float g1 = Prow[768 + t];

    __shared__ float sm[8], smp[8], smw[8];

    float m = fmaxf(s0, s1);
    #pragma unroll
    for (int o = 16; o; o >>= 1) m = fmaxf(m, __shfl_xor_sync(0xffffffffu, m, o));
    if (lane == 0) sm[wid] = m;
    __syncthreads();
    if (wid == 0) {
        float v = sm[lane & 7];
        #pragma unroll
        for (int o = 4; o; o >>= 1) v = fmaxf(v, __shfl_xor_sync(0xffffffffu, v, o));
        if (lane == 0) sm[0] = v;
    }
    __syncthreads();
    m = sm[0];

    float p0 = expf(s0 - m), p1 = expf(s1 - m);
    float ps = p0 + p1;
    float ws = p0 * (zbp[t] + g0) + p1 * (zbp[t + 256] + g1);
    #pragma unroll
    for (int o = 16; o; o >>= 1) {
        ps += __shfl_xor_sync(0xffffffffu, ps, o);
        ws += __shfl_xor_sync(0xffffffffu, ws, o);
    }
    if (lane == 0) { smp[wid] = ps; smw[wid] = ws; }
    __syncthreads();
    if (t == 0) {
        float tp = 0.f, tw = 0.f;
        #pragma unroll
        for (int i = 0; i < 8; i++) { tp += smp[i]; tw += smw[i]; }
        out[b * RR + r] = base[b * RR + r] + tw / tp;
    }
}

// ---------------- launch ----------------------------------------------------
extern "C" void kernel_launch(void* const* d_in, const int* in_sizes, int n_in,
                              void* d_out, int out_size)
{
    const float* X  = (const float*)d_in[0]; // [B,R,D]
    const float* Y  = (const float*)d_in[1]; // [B,T,D]
    const float* Wr = (const float*)d_in[2]; // [D,H]
    const float* br = (const float*)d_in[3]; // [H]
    const float* Wq = (const float*)d_in[4]; // [D,H]
    const float* bq = (const float*)d_in[5]; // [H] (only enters via softmax-invariant terms)
    const float* Ws = (const float*)d_in[6]; // [3D]
    const float* bs = (const float*)d_in[7]; // [1]
    float* out = (float*)d_out;
    (void)bq;

    float *P, *cb, *zb, *baseb, *wc;
    bf16 *Xh, *Xl, *Yh, *Yl, *Wrh, *Wrl, *Wqh, *Wql, *Mh, *Ml, *W2h, *W2l;
    cudaGetSymbolAddress((void**)&P, g_P);
    cudaGetSymbolAddress((void**)&cb, g_c);
    cudaGetSymbolAddress((void**)&zb, g_z);
    cudaGetSymbolAddress((void**)&baseb, g_base);
    cudaGetSymbolAddress((void**)&wc, g_wc);
    cudaGetSymbolAddress((void**)&Xh, g_Xh);   cudaGetSymbolAddress((void**)&Xl, g_Xl);
    cudaGetSymbolAddress((void**)&Yh, g_Yh);   cudaGetSymbolAddress((void**)&Yl, g_Yl);
    cudaGetSymbolAddress((void**)&Wrh, g_Wrh); cudaGetSymbolAddress((void**)&Wrl, g_Wrl);
    cudaGetSymbolAddress((void**)&Wqh, g_Wqh); cudaGetSymbolAddress((void**)&Wql, g_Wql);
    cudaGetSymbolAddress((void**)&Mh, g_Mh);   cudaGetSymbolAddress((void**)&Ml, g_Ml);
    cudaGetSymbolAddress((void**)&W2h, g_W2h); cudaGetSymbolAddress((void**)&W2l, g_W2l);

    const int BIG = 1 << 30;

    // input splits
    split_kernel<<<DD * HH / 1024, 256>>>((const float4*)Wr, (uint2*)Wrh, (uint2*)Wrl);
    split_kernel<<<DD * HH / 1024, 256>>>((const float4*)Wq, (uint2*)Wqh, (uint2*)Wql);
    split_kernel<<<BB * TT * DD / 1024, 256>>>((const float4*)Y, (uint2*)Yh, (uint2*)Yl);
    split_kernel<<<BB * RR * DD / 1024, 256>>>((const float4*)X, (uint2*)Xh, (uint2*)Xl);

    // M = Wr @ Wq^T (contraction over h), split-K x4 into g_P scratch, then reduce+split
    gemm_bf16_nt<0><<<dim3(8, 8, 4), 256>>>(
        Wrh, Wrl, Wqh, Wql, P, nullptr, nullptr,
        DD, 0LL, 0LL, (long long)DD * DD, 256, 256, BIG);
    reduce_split_kernel<<<DD * DD / 1024, 256>>>((const float4*)P, (uint2*)Mh, (uint2*)Ml);

    // aux vectors (exact fp32)
    rowdot_kernel<<<DD / 8, 256>>>(Wq, br, nullptr, wc, HH);            // wc = Wq @ br
    rowdot2_kernel<<<(BB * TT) / 8, 256>>>(Y, wc, Ws + DD, cb, zb);     // c[t]=Y·wc, z[t]=Y·Ws2
    rowdot_kernel<<<(BB * RR) / 8, 256>>>(X, Ws, bs, baseb, DD);        // base = X·Ws1 + bs

    // W2 bottom half = split(Y * ws3)
    yw_split_kernel<<<BB * TT * DD / 1024, 256>>>(
        (const float4*)Y, (const float4*)(Ws + 2 * DD), (uint2*)W2h, (uint2*)W2l);

    // V = Y @ M^T -> split-stored into W2 rows [0,512)  (per batch M=512, N=1024)
    gemm_bf16_nt<1><<<dim3(8, 4, BB), 256>>>(
        Yh, Yl, Mh, Ml, nullptr, W2h, W2l,
        DD, (long long)TT * DD, 0LL, (long long)2 * TT * DD, 1024, 0, BIG);

    // P = X @ W2^T  (per batch M=1024, N=1024); G columns (n>=512) use 2 phases
    gemm_bf16_nt<0><<<dim3(8, 8, BB), 256>>>(
        Xh, Xl, W2h, W2l, P, nullptr, nullptr,
        2 * TT, (long long)RR * DD, (long long)2 * TT * DD, (long long)RR * 2 * TT,
        1024, 0, 512);

    // softmax + fused epilogue
    softmax_out_kernel<<<dim3(RR, BB), 256>>>(P, cb, zb, baseb, out);
}

// round 8
// speedup vs baseline: 1.4803x; 1.4803x over previous
#include <cuda_runtime.h>
#include <cuda_bf16.h>
#include <cstdint>

// Problem constants
#define BB 16
#define RR 1024
#define TT 512
#define DD 1024
#define HH 1024

typedef __nv_bfloat16 bf16;

// ---------------- scratch (__device__ globals; no allocation allowed) -------
__device__ float g_P [BB * RR * 2 * TT];      // 64 MB (reused early as M split-K partials)
__device__ bf16  g_Xh[BB * RR * DD], g_Xl[BB * RR * DD];
__device__ bf16  g_Yh[BB * TT * DD], g_Yl[BB * TT * DD];
__device__ bf16  g_Wrh[DD * HH], g_Wrl[DD * HH];
__device__ bf16  g_Wqh[DD * HH], g_Wql[DD * HH];
__device__ bf16  g_Mh[DD * DD], g_Ml[DD * DD];
__device__ bf16  g_W2h[BB * 2 * TT * DD], g_W2l[BB * 2 * TT * DD];
__device__ float g_c[BB * TT], g_z[BB * TT], g_base[BB * RR];
__device__ float g_wc[DD];

// ---------------- helpers ---------------------------------------------------
__device__ __forceinline__ uint32_t smem_u32(const void* p) {
    return (uint32_t)__cvta_generic_to_shared(p);
}
__device__ __forceinline__ void cp16(void* s, const void* g) {
    asm volatile("cp.async.ca.shared.global [%0], [%1], 16;\n"
                 :: "r"(smem_u32(s)), "l"(g));
}
__device__ __forceinline__ void cp_commit() { asm volatile("cp.async.commit_group;\n"); }
template <int N>
__device__ __forceinline__ void cp_wait() { asm volatile("cp.async.wait_group %0;\n" :: "n"(N)); }

__device__ __forceinline__ void ldm_x4(uint32_t* r, uint32_t addr) {
    asm volatile("ldmatrix.sync.aligned.m8n8.x4.shared.b16 {%0,%1,%2,%3}, [%4];"
                 : "=r"(r[0]), "=r"(r[1]), "=r"(r[2]), "=r"(r[3]) : "r"(addr));
}
__device__ __forceinline__ void mma16816(float* d, const uint32_t* a, const uint32_t* b) {
    asm volatile(
        "mma.sync.aligned.m16n8k16.row.col.f32.bf16.bf16.f32 "
        "{%0,%1,%2,%3},{%4,%5,%6,%7},{%8,%9},{%0,%1,%2,%3};"
        : "+f"(d[0]), "+f"(d[1]), "+f"(d[2]), "+f"(d[3])
        : "r"(a[0]), "r"(a[1]), "r"(a[2]), "r"(a[3]), "r"(b[0]), "r"(b[1]));
}

__device__ __forceinline__ void split1(float v, bf16& h, bf16& l) {
    h = __float2bfloat16(v);
    l = __float2bfloat16(v - __bfloat162float(h));
}
__device__ __forceinline__ uint32_t pk2(bf16 a, bf16 b) {
    return (uint32_t)__bfloat16_as_ushort(a) | ((uint32_t)__bfloat16_as_ushort(b) << 16);
}

// ---------------- split kernels ---------------------------------------------
__global__ __launch_bounds__(256) void split_kernel(
    const float4* __restrict__ in, uint2* __restrict__ h, uint2* __restrict__ l)
{
    int i = blockIdx.x * 256 + threadIdx.x;
    float4 v = in[i];
    bf16 h0, l0, h1, l1, h2, l2, h3, l3;
    split1(v.x, h0, l0); split1(v.y, h1, l1); split1(v.z, h2, l2); split1(v.w, h3, l3);
    h[i] = make_uint2(pk2(h0, h1), pk2(h2, h3));
    l[i] = make_uint2(pk2(l0, l1), pk2(l2, l3));
}

// W2 bottom half: split(Y[b,t,d] * ws3[d]) -> W2h/W2l rows [512,1024)
__global__ __launch_bounds__(256) void yw_split_kernel(
    const float4* __restrict__ Y, const float4* __restrict__ ws3,
    uint2* __restrict__ W2h, uint2* __restrict__ W2l)
{
    int idx4 = blockIdx.x * 256 + threadIdx.x;   // [0, 16*512*1024/4)
    int d4 = idx4 & 255;
    int b  = idx4 >> 17;
    float4 y = Y[idx4];
    float4 w = ws3[d4];
    bf16 h0,l0,h1,l1,h2,l2,h3,l3;
    split1(y.x * w.x, h0, l0); split1(y.y * w.y, h1, l1);
    split1(y.z * w.z, h2, l2); split1(y.w * w.w, h3, l3);
    int o = idx4 + (b + 1) * 131072;
    W2h[o] = make_uint2(pk2(h0, h1), pk2(h2, h3));
    W2l[o] = make_uint2(pk2(l0, l1), pk2(l2, l3));
}

// reduce 4 split-K fp32 partials of M and split to bf16 h/l
__global__ __launch_bounds__(256) void reduce_split_kernel(
    const float4* __restrict__ part, uint2* __restrict__ h, uint2* __restrict__ l)
{
    int i = blockIdx.x * 256 + threadIdx.x;      // [0, 1024*1024/4)
    const int S = DD * DD / 4;
    float4 a = part[i], b = part[i + S], c = part[i + 2 * S], d = part[i + 3 * S];
    float4 v = make_float4(a.x + b.x + c.x + d.x, a.y + b.y + c.y + d.y,
                           a.z + b.z + c.z + d.z, a.w + b.w + c.w + d.w);
    bf16 h0, l0, h1, l1, h2, l2, h3, l3;
    split1(v.x, h0, l0); split1(v.y, h1, l1); split1(v.z, h2, l2); split1(v.w, h3, l3);
    h[i] = make_uint2(pk2(h0, h1), pk2(h2, h3));
    l[i] = make_uint2(pk2(l0, l1), pk2(l2, l3));
}

// ---------------- bf16 split NT GEMM (R3-proven inner loop) ------------------
// C[m,n] = sum over 3 phases: Ah*Bh + Al*Bh + Ah*Bl  (K per phase, row stride ld)
// EPI=0: fp32 store (+bias[n] if non-null). EPI=1: split-store bf16 into Ch/Cl.
template <int EPI>
__global__ __launch_bounds__(256, 2) void gemm_bf16_nt(
    const bf16* __restrict__ Ah, const bf16* __restrict__ Al,
    const bf16* __restrict__ Bh, const bf16* __restrict__ Bl,
    float* __restrict__ C, bf16* __restrict__ Ch, bf16* __restrict__ Cl,
    const float* __restrict__ bias,
    int K, int ld, int ldc, long long sA, long long sB, long long sC)
{
    const int bz = blockIdx.z;
    Ah += bz * sA; Al += bz * sA; Bh += bz * sB; Bl += bz * sB;

    const int m0 = blockIdx.y * 128, n0 = blockIdx.x * 128;
    const int tid = threadIdx.x, lane = tid & 31, wid = tid >> 5;
    const int wm = (wid & 1) * 64, wn = (wid >> 1) * 32;

    // [stage][0=A,1=B][128 rows * 40 bf16] (rows padded 32->40 for ldmatrix)
    __shared__ bf16 sm[2][2][128 * 40];

    float acc[4][4][4];
    #pragma unroll
    for (int i = 0; i < 4; i++)
        #pragma unroll
        for (int j = 0; j < 4; j++)
            #pragma unroll
            for (int q = 0; q < 4; q++) acc[i][j][q] = 0.f;

    const int ar0 = tid >> 2,          ak0 = (tid & 3) * 8;
    const int ar1 = (tid + 256) >> 2,  ak1 = ((tid + 256) & 3) * 8;

    const int nch = (3 * K) / 32;   // k-chunks over all 3 phases

    auto issue = [&](int chunk, int stage) {
        int kk = chunk * 32;
        int phase = kk / K, kin = kk - phase * K;
        const bf16* pA = (phase == 1) ? Al : Ah;
        const bf16* pB = (phase == 2) ? Bl : Bh;
        cp16(&sm[stage][0][ar0 * 40 + ak0], pA + (long long)(m0 + ar0) * ld + kin + ak0);
        cp16(&sm[stage][0][ar1 * 40 + ak1], pA + (long long)(m0 + ar1) * ld + kin + ak1);
        cp16(&sm[stage][1][ar0 * 40 + ak0], pB + (long long)(n0 + ar0) * ld + kin + ak0);
        cp16(&sm[stage][1][ar1 * 40 + ak1], pB + (long long)(n0 + ar1) * ld + kin + ak1);
        cp_commit();
    };

    issue(0, 0);

    const int aRow = lane & 15, aKof = (lane >> 4) * 8;
    const int bRow = ((lane >> 4) << 3) + (lane & 7), bKof = ((lane >> 3) & 1) * 8;

    for (int c = 0; c < nch; c++) {
        int st = c & 1;
        if (c + 1 < nch) { issue(c + 1, st ^ 1); cp_wait<1>(); }
        else             { cp_wait<0>(); }
        __syncthreads();

        #pragma unroll
        for (int ks = 0; ks < 32; ks += 16) {
            uint32_t af[4][4];
            #pragma unroll
            for (int mt = 0; mt < 4; mt++)
                ldm_x4(af[mt], smem_u32(&sm[st][0][(wm + mt * 16 + aRow) * 40 + ks + aKof]));
            uint32_t bfr[2][4];
            #pragma unroll
            for (int bt = 0; bt < 2; bt++)
                ldm_x4(bfr[bt], smem_u32(&sm[st][1][(wn + bt * 16 + bRow) * 40 + ks + bKof]));
            #pragma unroll
            for (int mt = 0; mt < 4; mt++) {
                #pragma unroll
                for (int nt = 0; nt < 4; nt++) {
                    mma16816(acc[mt][nt], af[mt], &bfr[nt >> 1][(nt & 1) * 2]);
                }
            }
        }
        __syncthreads();
    }

    // epilogue
    const int tg = lane >> 2, tl = lane & 3;
    #pragma unroll
    for (int mt = 0; mt < 4; mt++) {
        #pragma unroll
        for (int nt = 0; nt < 4; nt++) {
            int m = m0 + wm + mt * 16 + tg;
            int n = n0 + wn + nt * 8 + 2 * tl;
            float v0 = acc[mt][nt][0], v1 = acc[mt][nt][1];
            float v2 = acc[mt][nt][2], v3 = acc[mt][nt][3];
            if (EPI == 0) {
                if (bias) { v0 += bias[n]; v1 += bias[n + 1]; v2 += bias[n]; v3 += bias[n + 1]; }
                float* Cb = C + bz * sC;
                *reinterpret_cast<float2*>(&Cb[(long long)m * ldc + n])       = make_float2(v0, v1);
                *reinterpret_cast<float2*>(&Cb[(long long)(m + 8) * ldc + n]) = make_float2(v2, v3);
            } else {
                bf16 h0,l0,h1,l1,h2,l2,h3,l3;
                split1(v0, h0, l0); split1(v1, h1, l1); split1(v2, h2, l2); split1(v3, h3, l3);
                bf16* Hb = Ch + bz * sC; bf16* Lb = Cl + bz * sC;
                *reinterpret_cast<uint32_t*>(&Hb[(long long)m * ldc + n])       = pk2(h0, h1);
                *reinterpret_cast<uint32_t*>(&Lb[(long long)m * ldc + n])       = pk2(l0, l1);
                *reinterpret_cast<uint32_t*>(&Hb[(long long)(m + 8) * ldc + n]) = pk2(h2, h3);
                *reinterpret_cast<uint32_t*>(&Lb[(long long)(m + 8) * ldc + n]) = pk2(l2, l3);
            }
        }
    }
}

// ---------------- aux kernels (fp32) ----------------------------------------
__global__ __launch_bounds__(256) void rowdot_kernel(
    const float* __restrict__ A, const float* __restrict__ v,
    const float* __restrict__ addp, float* __restrict__ out, int K)
{
    int row = blockIdx.x * 8 + (threadIdx.x >> 5);
    int lane = threadIdx.x & 31;
    const float* a = A + (long long)row * K;
    float s = 0.f;
    for (int i = lane * 4; i < K; i += 128) {
        float4 x = *reinterpret_cast<const float4*>(&a[i]);
        float4 w = *reinterpret_cast<const float4*>(&v[i]);
        s += x.x * w.x + x.y * w.y + x.z * w.z + x.w * w.w;
    }
    #pragma unroll
    for (int o = 16; o; o >>= 1) s += __shfl_xor_sync(0xffffffffu, s, o);
    if (lane == 0) out[row] = s + (addp ? addp[0] : 0.f);
}

// c[row] = Y[row]·wc ; z[row] = Y[row]·w2
__global__ __launch_bounds__(256) void rowdot2_kernel(
    const float* __restrict__ Y, const float* __restrict__ wc,
    const float* __restrict__ w2, float* __restrict__ cb, float* __restrict__ zb)
{
    int row = blockIdx.x * 8 + (threadIdx.x >> 5);
    int lane = threadIdx.x & 31;
    const float* a = Y + (long long)row * DD;
    float s1 = 0.f, s2 = 0.f;
    for (int i = lane * 4; i < DD; i += 128) {
        float4 x = *reinterpret_cast<const float4*>(&a[i]);
        float4 u = *reinterpret_cast<const float4*>(&wc[i]);
        float4 v = *reinterpret_cast<const float4*>(&w2[i]);
        s1 += x.x * u.x + x.y * u.y + x.z * u.z + x.w * u.w;
        s2 += x.x * v.x + x.y * v.y + x.z * v.z + x.w * v.w;
    }
    #pragma unroll
    for (int o = 16; o; o >>= 1) {
        s1 += __shfl_xor_sync(0xffffffffu, s1, o);
        s2 += __shfl_xor_sync(0xffffffffu, s2, o);
    }
    if (lane == 0) { cb[row] = s1; zb[row] = s2; }
}

__global__ __launch_bounds__(256) void softmax_out_kernel(
    const float* __restrict__ P, const float* __restrict__ c,
    const float* __restrict__ z, const float* __restrict__ base,
    float* __restrict__ out)
{
    const int b = blockIdx.y, r = blockIdx.x;
    const float* Prow = P + ((long long)b * RR + r) * (2 * TT);
    const float* cbp = c + b * TT;
    const float* zbp = z + b * TT;
    const int t = threadIdx.x;
    const int lane = t & 31, wid = t >> 5;

    float s0 = Prow[t]       + cbp[t];
    float s1 = Prow[t + 256] + cbp[t + 256];
    float g0 = Prow[512 + t];
    float g1 = Prow[768 + t];

    __shared__ float sm[8], smp[8], smw[8];

    float m = fmaxf(s0, s1);
    #pragma unroll
    for (int o = 16; o; o >>= 1) m = fmaxf(m, __shfl_xor_sync(0xffffffffu, m, o));
    if (lane == 0) sm[wid] = m;
    __syncthreads();
    if (wid == 0) {
        float v = sm[lane & 7];
        #pragma unroll
        for (int o = 4; o; o >>= 1) v = fmaxf(v, __shfl_xor_sync(0xffffffffu, v, o));
        if (lane == 0) sm[0] = v;
    }
    __syncthreads();
    m = sm[0];

    float p0 = expf(s0 - m), p1 = expf(s1 - m);
    float ps = p0 + p1;
    float ws = p0 * (zbp[t] + g0) + p1 * (zbp[t + 256] + g1);
    #pragma unroll
    for (int o = 16; o; o >>= 1) {
        ps += __shfl_xor_sync(0xffffffffu, ps, o);
        ws += __shfl_xor_sync(0xffffffffu, ws, o);
    }
    if (lane == 0) { smp[wid] = ps; smw[wid] = ws; }
    __syncthreads();
    if (t == 0) {
        float tp = 0.f, tw = 0.f;
        #pragma unroll
        for (int i = 0; i < 8; i++) { tp += smp[i]; tw += smw[i]; }
        out[b * RR + r] = base[b * RR + r] + tw / tp;
    }
}

// ---------------- launch ----------------------------------------------------
extern "C" void kernel_launch(void* const* d_in, const int* in_sizes, int n_in,
                              void* d_out, int out_size)
{
    const float* X  = (const float*)d_in[0]; // [B,R,D]
    const float* Y  = (const float*)d_in[1]; // [B,T,D]
    const float* Wr = (const float*)d_in[2]; // [D,H]
    const float* br = (const float*)d_in[3]; // [H]
    const float* Wq = (const float*)d_in[4]; // [D,H]
    const float* bq = (const float*)d_in[5]; // [H] (enters only via softmax-invariant terms)
    const float* Ws = (const float*)d_in[6]; // [3D]
    const float* bs = (const float*)d_in[7]; // [1]
    float* out = (float*)d_out;
    (void)bq;

    float *P, *cb, *zb, *baseb, *wc;
    bf16 *Xh, *Xl, *Yh, *Yl, *Wrh, *Wrl, *Wqh, *Wql, *Mh, *Ml, *W2h, *W2l;
    cudaGetSymbolAddress((void**)&P, g_P);
    cudaGetSymbolAddress((void**)&cb, g_c);
    cudaGetSymbolAddress((void**)&zb, g_z);
    cudaGetSymbolAddress((void**)&baseb, g_base);
    cudaGetSymbolAddress((void**)&wc, g_wc);
    cudaGetSymbolAddress((void**)&Xh, g_Xh);   cudaGetSymbolAddress((void**)&Xl, g_Xl);
    cudaGetSymbolAddress((void**)&Yh, g_Yh);   cudaGetSymbolAddress((void**)&Yl, g_Yl);
    cudaGetSymbolAddress((void**)&Wrh, g_Wrh); cudaGetSymbolAddress((void**)&Wrl, g_Wrl);
    cudaGetSymbolAddress((void**)&Wqh, g_Wqh); cudaGetSymbolAddress((void**)&Wql, g_Wql);
    cudaGetSymbolAddress((void**)&Mh, g_Mh);   cudaGetSymbolAddress((void**)&Ml, g_Ml);
    cudaGetSymbolAddress((void**)&W2h, g_W2h); cudaGetSymbolAddress((void**)&W2l, g_W2l);

    // input splits
    split_kernel<<<DD * HH / 1024, 256>>>((const float4*)Wr, (uint2*)Wrh, (uint2*)Wrl);
    split_kernel<<<DD * HH / 1024, 256>>>((const float4*)Wq, (uint2*)Wqh, (uint2*)Wql);
    split_kernel<<<BB * TT * DD / 1024, 256>>>((const float4*)Y, (uint2*)Yh, (uint2*)Yl);
    split_kernel<<<BB * RR * DD / 1024, 256>>>((const float4*)X, (uint2*)Xh, (uint2*)Xl);

    // M = Wr @ Wq^T (contraction over h): split-K x4 via sA=sB=256 (k-offset per bz),
    // partials into g_P scratch, then reduce + split to bf16 h/l.
    gemm_bf16_nt<0><<<dim3(8, 8, 4), 256>>>(
        Wrh, Wrl, Wqh, Wql, P, nullptr, nullptr, nullptr,
        256, HH, DD, 256LL, 256LL, (long long)DD * DD);
    reduce_split_kernel<<<DD * DD / 1024, 256>>>((const float4*)P, (uint2*)Mh, (uint2*)Ml);

    // aux vectors (exact fp32)
    rowdot_kernel<<<DD / 8, 256>>>(Wq, br, nullptr, wc, HH);            // wc = Wq @ br
    rowdot2_kernel<<<(BB * TT) / 8, 256>>>(Y, wc, Ws + DD, cb, zb);     // c[t]=Y·wc, z[t]=Y·Ws2
    rowdot_kernel<<<(BB * RR) / 8, 256>>>(X, Ws, bs, baseb, DD);        // base = X·Ws1 + bs

    // W2 bottom half = split(Y * ws3)
    yw_split_kernel<<<BB * TT * DD / 1024, 256>>>(
        (const float4*)Y, (const float4*)(Ws + 2 * DD), (uint2*)W2h, (uint2*)W2l);

    // V = Y @ M^T -> split-stored into W2 rows [0,512)  (per batch M=512, N=1024)
    gemm_bf16_nt<1><<<dim3(8, 4, BB), 256>>>(
        Yh, Yl, Mh, Ml, nullptr, W2h, W2l, nullptr,
        DD, DD, DD, (long long)TT * DD, 0LL, (long long)2 * TT * DD);

    // P = X @ W2^T  (per batch M=1024, N=1024), full 3-phase everywhere
    gemm_bf16_nt<0><<<dim3(8, 8, BB), 256>>>(
        Xh, Xl, W2h, W2l, P, nullptr, nullptr, nullptr,
        DD, DD, 2 * TT, (long long)RR * DD, (long long)2 * TT * DD, (long long)RR * 2 * TT);

    // softmax + fused epilogue
    softmax_out_kernel<<<dim3(RR, BB), 256>>>(P, cb, zb, baseb, out);
}

// round 9
// speedup vs baseline: 1.5833x; 1.0696x over previous
#include <cuda_runtime.h>
#include <cuda_fp16.h>
#include <cstdint>

// Problem constants
#define BB 16
#define RR 1024
#define TT 512
#define DD 1024
#define HH 1024

typedef __half h16;

// ---------------- scratch (__device__ globals; no allocation allowed) -------
__device__ float g_P [BB * RR * 2 * TT];      // 64 MB (reused early as M split-K partials)
__device__ h16   g_Xh[BB * RR * DD], g_Xl[BB * RR * DD];
__device__ h16   g_Yh[BB * TT * DD], g_Yl[BB * TT * DD];
__device__ h16   g_Wrh[DD * HH], g_Wrl[DD * HH];
__device__ h16   g_Wqh[DD * HH], g_Wql[DD * HH];
__device__ h16   g_Mh[DD * DD], g_Ml[DD * DD];
__device__ h16   g_W2h[BB * 2 * TT * DD], g_W2l[BB * 2 * TT * DD];
__device__ float g_c[BB * TT], g_z[BB * TT], g_base[BB * RR];
__device__ float g_wc[DD];

// ---------------- helpers ---------------------------------------------------
__device__ __forceinline__ uint32_t smem_u32(const void* p) {
    return (uint32_t)__cvta_generic_to_shared(p);
}
__device__ __forceinline__ void cp16(void* s, const void* g) {
    asm volatile("cp.async.ca.shared.global [%0], [%1], 16;\n"
                 :: "r"(smem_u32(s)), "l"(g));
}
__device__ __forceinline__ void cp_commit() { asm volatile("cp.async.commit_group;\n"); }
template <int N>
__device__ __forceinline__ void cp_wait() { asm volatile("cp.async.wait_group %0;\n" :: "n"(N)); }

__device__ __forceinline__ void ldm_x4(uint32_t* r, uint32_t addr) {
    asm volatile("ldmatrix.sync.aligned.m8n8.x4.shared.b16 {%0,%1,%2,%3}, [%4];"
                 : "=r"(r[0]), "=r"(r[1]), "=r"(r[2]), "=r"(r[3]) : "r"(addr));
}
__device__ __forceinline__ void mma16816(float* d, const uint32_t* a, const uint32_t* b) {
    asm volatile(
        "mma.sync.aligned.m16n8k16.row.col.f32.f16.f16.f32 "
        "{%0,%1,%2,%3},{%4,%5,%6,%7},{%8,%9},{%0,%1,%2,%3};"
        : "+f"(d[0]), "+f"(d[1]), "+f"(d[2]), "+f"(d[3])
        : "r"(a[0]), "r"(a[1]), "r"(a[2]), "r"(a[3]), "r"(b[0]), "r"(b[1]));
}

__device__ __forceinline__ void split1(float v, h16& h, h16& l) {
    h = __float2half_rn(v);
    l = __float2half_rn(v - __half2float(h));
}
__device__ __forceinline__ uint32_t pk2(h16 a, h16 b) {
    return (uint32_t)__half_as_ushort(a) | ((uint32_t)__half_as_ushort(b) << 16);
}

// ---------------- split / fused prep kernels ---------------------------------
__global__ __launch_bounds__(256) void split_kernel(
    const float4* __restrict__ in, uint2* __restrict__ h, uint2* __restrict__ l)
{
    int i = blockIdx.x * 256 + threadIdx.x;
    float4 v = in[i];
    h16 h0, l0, h1, l1, h2, l2, h3, l3;
    split1(v.x, h0, l0); split1(v.y, h1, l1); split1(v.z, h2, l2); split1(v.w, h3, l3);
    h[i] = make_uint2(pk2(h0, h1), pk2(h2, h3));
    l[i] = make_uint2(pk2(l0, l1), pk2(l2, l3));
}

// X prep: one block per row. Split X -> Xh/Xl and base[row] = X·Ws1 + bs.
__global__ __launch_bounds__(256) void xprep_kernel(
    const float4* __restrict__ X, const float4* __restrict__ ws1,
    const float* __restrict__ bs,
    uint2* __restrict__ Xh, uint2* __restrict__ Xl, float* __restrict__ base)
{
    const int row = blockIdx.x, t = threadIdx.x;
    const int i = row * 256 + t;
    float4 v = X[i];
    h16 h0, l0, h1, l1, h2, l2, h3, l3;
    split1(v.x, h0, l0); split1(v.y, h1, l1); split1(v.z, h2, l2); split1(v.w, h3, l3);
    Xh[i] = make_uint2(pk2(h0, h1), pk2(h2, h3));
    Xl[i] = make_uint2(pk2(l0, l1), pk2(l2, l3));

    float4 w = ws1[t];
    float s = v.x * w.x + v.y * w.y + v.z * w.z + v.w * w.w;
    __shared__ float red[8];
    #pragma unroll
    for (int o = 16; o; o >>= 1) s += __shfl_xor_sync(0xffffffffu, s, o);
    if ((t & 31) == 0) red[t >> 5] = s;
    __syncthreads();
    if (t == 0) {
        float r = 0.f;
        #pragma unroll
        for (int k = 0; k < 8; k++) r += red[k];
        base[row] = r + bs[0];
    }
}

// Y prep: one block per (b,t) row. Split Y -> Yh/Yl; split(Y*ws3) -> W2 bottom row;
// c[row] = Y·wc; z[row] = Y·Ws2.
__global__ __launch_bounds__(256) void yprep_kernel(
    const float4* __restrict__ Y, const float4* __restrict__ Ws,
    const float4* __restrict__ wc,
    uint2* __restrict__ Yh, uint2* __restrict__ Yl,
    uint2* __restrict__ W2h, uint2* __restrict__ W2l,
    float* __restrict__ cb, float* __restrict__ zb)
{
    const int row = blockIdx.x, t = threadIdx.x;     // row in [0, 8192)
    const int b = row >> 9, tt = row & 511;
    const int i = row * 256 + t;
    float4 v = Y[i];
    h16 h0, l0, h1, l1, h2, l2, h3, l3;
    split1(v.x, h0, l0); split1(v.y, h1, l1); split1(v.z, h2, l2); split1(v.w, h3, l3);
    Yh[i] = make_uint2(pk2(h0, h1), pk2(h2, h3));
    Yl[i] = make_uint2(pk2(l0, l1), pk2(l2, l3));

    float4 w3 = Ws[512 + t];                          // ws3 = Ws + 2048 floats
    split1(v.x * w3.x, h0, l0); split1(v.y * w3.y, h1, l1);
    split1(v.z * w3.z, h2, l2); split1(v.w * w3.w, h3, l3);
    const int o = (b * 1024 + 512 + tt) * 256 + t;    // W2 bottom row, uint2 units
    W2h[o] = make_uint2(pk2(h0, h1), pk2(h2, h3));
    W2l[o] = make_uint2(pk2(l0, l1), pk2(l2, l3));

    float4 u = wc[t];
    float4 w2 = Ws[256 + t];                          // ws2 = Ws + 1024 floats
    float s1 = v.x * u.x + v.y * u.y + v.z * u.z + v.w * u.w;
    float s2 = v.x * w2.x + v.y * w2.y + v.z * w2.z + v.w * w2.w;
    __shared__ float r1[8], r2[8];
    #pragma unroll
    for (int o2 = 16; o2; o2 >>= 1) {
        s1 += __shfl_xor_sync(0xffffffffu, s1, o2);
        s2 += __shfl_xor_sync(0xffffffffu, s2, o2);
    }
    if ((t & 31) == 0) { r1[t >> 5] = s1; r2[t >> 5] = s2; }
    __syncthreads();
    if (t == 0) {
        float a1 = 0.f, a2 = 0.f;
        #pragma unroll
        for (int k = 0; k < 8; k++) { a1 += r1[k]; a2 += r2[k]; }
        cb[row] = a1; zb[row] = a2;
    }
}

// reduce 4 split-K fp32 partials of M and split to h/l
__global__ __launch_bounds__(256) void reduce_split_kernel(
    const float4* __restrict__ part, uint2* __restrict__ h, uint2* __restrict__ l)
{
    int i = blockIdx.x * 256 + threadIdx.x;
    const int S = DD * DD / 4;
    float4 a = part[i], b = part[i + S], c = part[i + 2 * S], d = part[i + 3 * S];
    float4 v = make_float4(a.x + b.x + c.x + d.x, a.y + b.y + c.y + d.y,
                           a.z + b.z + c.z + d.z, a.w + b.w + c.w + d.w);
    h16 h0, l0, h1, l1, h2, l2, h3, l3;
    split1(v.x, h0, l0); split1(v.y, h1, l1); split1(v.z, h2, l2); split1(v.w, h3, l3);
    h[i] = make_uint2(pk2(h0, h1), pk2(h2, h3));
    l[i] = make_uint2(pk2(l0, l1), pk2(l2, l3));
}

// ---------------- fp16 split NT GEMM (R3/R8-proven inner loop) ---------------
// C[m,n] = sum over NPH phases: (0) Ah*Bh, (1) Al*Bh, (2) Ah*Bl. K per phase, row stride ld.
// EPI=0: fp32 store. EPI=1: split-store h16 into Ch/Cl.
template <int EPI, int NPH>
__global__ __launch_bounds__(256, 2) void gemm_h16_nt(
    const h16* __restrict__ Ah, const h16* __restrict__ Al,
    const h16* __restrict__ Bh, const h16* __restrict__ Bl,
    float* __restrict__ C, h16* __restrict__ Ch, h16* __restrict__ Cl,
    int K, int ld, int ldc, long long sA, long long sB, long long sC)
{
    const int bz = blockIdx.z;
    Ah += bz * sA; Al += bz * sA; Bh += bz * sB; Bl += bz * sB;

    const int m0 = blockIdx.y * 128, n0 = blockIdx.x * 128;
    const int tid = threadIdx.x, lane = tid & 31, wid = tid >> 5;
    const int wm = (wid & 1) * 64, wn = (wid >> 1) * 32;

    __shared__ h16 sm[2][2][128 * 40];

    float acc[4][4][4];
    #pragma unroll
    for (int i = 0; i < 4; i++)
        #pragma unroll
        for (int j = 0; j < 4; j++)
            #pragma unroll
            for (int q = 0; q < 4; q++) acc[i][j][q] = 0.f;

    const int ar0 = tid >> 2,          ak0 = (tid & 3) * 8;
    const int ar1 = (tid + 256) >> 2,  ak1 = ((tid + 256) & 3) * 8;

    const int nch = (NPH * K) / 32;

    auto issue = [&](int chunk, int stage) {
        int kk = chunk * 32;
        int phase = kk / K, kin = kk - phase * K;
        const h16* pA = (phase == 1) ? Al : Ah;
        const h16* pB = (phase == 2) ? Bl : Bh;
        cp16(&sm[stage][0][ar0 * 40 + ak0], pA + (long long)(m0 + ar0) * ld + kin + ak0);
        cp16(&sm[stage][0][ar1 * 40 + ak1], pA + (long long)(m0 + ar1) * ld + kin + ak1);
        cp16(&sm[stage][1][ar0 * 40 + ak0], pB + (long long)(n0 + ar0) * ld + kin + ak0);
        cp16(&sm[stage][1][ar1 * 40 + ak1], pB + (long long)(n0 + ar1) * ld + kin + ak1);
        cp_commit();
    };

    issue(0, 0);

    const int aRow = lane & 15, aKof = (lane >> 4) * 8;
    const int bRow = ((lane >> 4) << 3) + (lane & 7), bKof = ((lane >> 3) & 1) * 8;

    for (int c = 0; c < nch; c++) {
        int st = c & 1;
        if (c + 1 < nch) { issue(c + 1, st ^ 1); cp_wait<1>(); }
        else             { cp_wait<0>(); }
        __syncthreads();

        #pragma unroll
        for (int ks = 0; ks < 32; ks += 16) {
            uint32_t af[4][4];
            #pragma unroll
            for (int mt = 0; mt < 4; mt++)
                ldm_x4(af[mt], smem_u32(&sm[st][0][(wm + mt * 16 + aRow) * 40 + ks + aKof]));
            uint32_t bfr[2][4];
            #pragma unroll
            for (int bt = 0; bt < 2; bt++)
                ldm_x4(bfr[bt], smem_u32(&sm[st][1][(wn + bt * 16 + bRow) * 40 + ks + bKof]));
            #pragma unroll
            for (int mt = 0; mt < 4; mt++) {
                #pragma unroll
                for (int nt = 0; nt < 4; nt++) {
                    mma16816(acc[mt][nt], af[mt], &bfr[nt >> 1][(nt & 1) * 2]);
                }
            }
        }
        __syncthreads();
    }

    // epilogue
    const int tg = lane >> 2, tl = lane & 3;
    #pragma unroll
    for (int mt = 0; mt < 4; mt++) {
        #pragma unroll
        for (int nt = 0; nt < 4; nt++) {
            int m = m0 + wm + mt * 16 + tg;
            int n = n0 + wn + nt * 8 + 2 * tl;
            float v0 = acc[mt][nt][0], v1 = acc[mt][nt][1];
            float v2 = acc[mt][nt][2], v3 = acc[mt][nt][3];
            if (EPI == 0) {
                float* Cb = C + bz * sC;
                *reinterpret_cast<float2*>(&Cb[(long long)m * ldc + n])       = make_float2(v0, v1);
                *reinterpret_cast<float2*>(&Cb[(long long)(m + 8) * ldc + n]) = make_float2(v2, v3);
            } else {
                h16 h0,l0,h1,l1,h2,l2,h3,l3;
                split1(v0, h0, l0); split1(v1, h1, l1); split1(v2, h2, l2); split1(v3, h3, l3);
                h16* Hb = Ch + bz * sC; h16* Lb = Cl + bz * sC;
                *reinterpret_cast<uint32_t*>(&Hb[(long long)m * ldc + n])       = pk2(h0, h1);
                *reinterpret_cast<uint32_t*>(&Lb[(long long)m * ldc + n])       = pk2(l0, l1);
                *reinterpret_cast<uint32_t*>(&Hb[(long long)(m + 8) * ldc + n]) = pk2(h2, h3);
                *reinterpret_cast<uint32_t*>(&Lb[(long long)(m + 8) * ldc + n]) = pk2(l2, l3);
            }
        }
    }
}

// ---------------- aux kernels (fp32) ----------------------------------------
__global__ __launch_bounds__(256) void rowdot_kernel(
    const float* __restrict__ A, const float* __restrict__ v,
    const float* __restrict__ addp, float* __restrict__ out, int K)
{
    int row = blockIdx.x * 8 + (threadIdx.x >> 5);
    int lane = threadIdx.x & 31;
    const float* a = A + (long long)row * K;
    float s = 0.f;
    for (int i = lane * 4; i < K; i += 128) {
        float4 x = *reinterpret_cast<const float4*>(&a[i]);
        float4 w = *reinterpret_cast<const float4*>(&v[i]);
        s += x.x * w.x + x.y * w.y + x.z * w.z + x.w * w.w;
    }
    #pragma unroll
    for (int o = 16; o; o >>= 1) s += __shfl_xor_sync(0xffffffffu, s, o);
    if (lane == 0) out[row] = s + (addp ? addp[0] : 0.f);
}

__global__ __launch_bounds__(256) void softmax_out_kernel(
    const float* __restrict__ P, const float* __restrict__ c,
    const float* __restrict__ z, const float* __restrict__ base,
    float* __restrict__ out)
{
    const int b = blockIdx.y, r = blockIdx.x;
    const float* Prow = P + ((long long)b * RR + r) * (2 * TT);
    const float* cbp = c + b * TT;
    const float* zbp = z + b * TT;
    const int t = threadIdx.x;
    const int lane = t & 31, wid = t >> 5;

    float s0 = Prow[t]       + cbp[t];
    float s1 = Prow[t + 256] + cbp[t + 256];
    float g0 = Prow[512 + t];
    float g1 = Prow[768 + t];

    __shared__ float sm[8], smp[8], smw[8];

    float m = fmaxf(s0, s1);
    #pragma unroll
    for (int o = 16; o; o >>= 1) m = fmaxf(m, __shfl_xor_sync(0xffffffffu, m, o));
    if (lane == 0) sm[wid] = m;
    __syncthreads();
    if (wid == 0) {
        float v = sm[lane & 7];
        #pragma unroll
        for (int o = 4; o; o >>= 1) v = fmaxf(v, __shfl_xor_sync(0xffffffffu, v, o));
        if (lane == 0) sm[0] = v;
    }
    __syncthreads();
    m = sm[0];

    float p0 = expf(s0 - m), p1 = expf(s1 - m);
    float ps = p0 + p1;
    float ws = p0 * (zbp[t] + g0) + p1 * (zbp[t + 256] + g1);
    #pragma unroll
    for (int o = 16; o; o >>= 1) {
        ps += __shfl_xor_sync(0xffffffffu, ps, o);
        ws += __shfl_xor_sync(0xffffffffu, ws, o);
    }
    if (lane == 0) { smp[wid] = ps; smw[wid] = ws; }
    __syncthreads();
    if (t == 0) {
        float tp = 0.f, tw = 0.f;
        #pragma unroll
        for (int i = 0; i < 8; i++) { tp += smp[i]; tw += smw[i]; }
        out[b * RR + r] = base[b * RR + r] + tw / tp;
    }
}

// ---------------- launch ----------------------------------------------------
extern "C" void kernel_launch(void* const* d_in, const int* in_sizes, int n_in,
                              void* d_out, int out_size)
{
    const float* X  = (const float*)d_in[0]; // [B,R,D]
    const float* Y  = (const float*)d_in[1]; // [B,T,D]
    const float* Wr = (const float*)d_in[2]; // [D,H]
    const float* br = (const float*)d_in[3]; // [H]
    const float* Wq = (const float*)d_in[4]; // [D,H]
    const float* bq = (const float*)d_in[5]; // [H] (enters only via softmax-invariant terms)
    const float* Ws = (const float*)d_in[6]; // [3D]
    const float* bs = (const float*)d_in[7]; // [1]
    float* out = (float*)d_out;
    (void)bq;

    float *P, *cb, *zb, *baseb, *wc;
    h16 *Xh, *Xl, *Yh, *Yl, *Wrh, *Wrl, *Wqh, *Wql, *Mh, *Ml, *W2h, *W2l;
    cudaGetSymbolAddress((void**)&P, g_P);
    cudaGetSymbolAddress((void**)&cb, g_c);
    cudaGetSymbolAddress((void**)&zb, g_z);
    cudaGetSymbolAddress((void**)&baseb, g_base);
    cudaGetSymbolAddress((void**)&wc, g_wc);
    cudaGetSymbolAddress((void**)&Xh, g_Xh);   cudaGetSymbolAddress((void**)&Xl, g_Xl);
    cudaGetSymbolAddress((void**)&Yh, g_Yh);   cudaGetSymbolAddress((void**)&Yl, g_Yl);
    cudaGetSymbolAddress((void**)&Wrh, g_Wrh); cudaGetSymbolAddress((void**)&Wrl, g_Wrl);
    cudaGetSymbolAddress((void**)&Wqh, g_Wqh); cudaGetSymbolAddress((void**)&Wql, g_Wql);
    cudaGetSymbolAddress((void**)&Mh, g_Mh);   cudaGetSymbolAddress((void**)&Ml, g_Ml);
    cudaGetSymbolAddress((void**)&W2h, g_W2h); cudaGetSymbolAddress((void**)&W2l, g_W2l);

    // weight splits
    split_kernel<<<DD * HH / 1024, 256>>>((const float4*)Wr, (uint2*)Wrh, (uint2*)Wrl);
    split_kernel<<<DD * HH / 1024, 256>>>((const float4*)Wq, (uint2*)Wqh, (uint2*)Wql);

    // M = Wr @ Wq^T (contraction over h): split-K x4 (k-offset 256 per bz) into g_P
    // scratch, then reduce + split to h/l.
    gemm_h16_nt<0, 3><<<dim3(8, 8, 4), 256>>>(
        Wrh, Wrl, Wqh, Wql, P, nullptr, nullptr,
        256, HH, DD, 256LL, 256LL, (long long)DD * DD);
    reduce_split_kernel<<<DD * DD / 1024, 256>>>((const float4*)P, (uint2*)Mh, (uint2*)Ml);

    // wc = Wq @ br (exact fp32)
    rowdot_kernel<<<DD / 8, 256>>>(Wq, br, nullptr, wc, HH);

    // fused prep: X split + base; Y split + W2 bottom + c/z
    xprep_kernel<<<BB * RR, 256>>>((const float4*)X, (const float4*)Ws, bs,
                                   (uint2*)Xh, (uint2*)Xl, baseb);
    yprep_kernel<<<BB * TT, 256>>>((const float4*)Y, (const float4*)Ws, (const float4*)wc,
                                   (uint2*)Yh, (uint2*)Yl, (uint2*)W2h, (uint2*)W2l, cb, zb);

    // V = Y @ M^T -> split-stored into W2 rows [0,512)  (per batch M=512, N=1024), 3-phase
    gemm_h16_nt<1, 3><<<dim3(8, 4, BB), 256>>>(
        Yh, Yl, Mh, Ml, nullptr, W2h, W2l,
        DD, DD, DD, (long long)TT * DD, 0LL, (long long)2 * TT * DD);

    // P (S half) = X @ V^T : cols [0,512), 3-phase
    gemm_h16_nt<0, 3><<<dim3(4, 8, BB), 256>>>(
        Xh, Xl, W2h, W2l, P, nullptr, nullptr,
        DD, DD, 2 * TT, (long long)RR * DD, (long long)2 * TT * DD, (long long)RR * 2 * TT);

    // P (G half) = X @ Yw^T : cols [512,1024), 2-phase (hh + lh; W2l never read)
    gemm_h16_nt<0, 2><<<dim3(4, 8, BB), 256>>>(
        Xh, Xl, W2h + (long long)512 * DD, W2l + (long long)512 * DD, P + 512, nullptr, nullptr,
        DD, DD, 2 * TT, (long long)RR * DD, (long long)2 * TT * DD, (long long)RR * 2 * TT);

    // softmax + fused epilogue
    softmax_out_kernel<<<dim3(RR, BB), 256>>>(P, cb, zb, baseb, out);
}

// round 10
// speedup vs baseline: 1.7556x; 1.1088x over previous
#include <cuda_runtime.h>
#include <cuda_fp16.h>
#include <cstdint>

// Problem constants
#define BB 16
#define RR 1024
#define TT 512
#define DD 1024
#define HH 1024

typedef __half h16;

// ---------------- scratch (__device__ globals; no allocation allowed) -------
__device__ float g_P [BB * RR * 2 * TT];      // 64 MB (reused early as M split-K partials)
__device__ h16   g_Xh[BB * RR * DD], g_Xl[BB * RR * DD];
__device__ h16   g_Yh[BB * TT * DD], g_Yl[BB * TT * DD];
__device__ h16   g_Wrh[DD * HH], g_Wrl[DD * HH];
__device__ h16   g_Wqh[DD * HH], g_Wql[DD * HH];
__device__ h16   g_Mh[DD * DD], g_Ml[DD * DD];
__device__ h16   g_W2h[BB * 2 * TT * DD], g_W2l[BB * 2 * TT * DD];
__device__ float g_c[BB * TT], g_z[BB * TT], g_base[BB * RR];
__device__ float g_wc[DD];

// ---------------- helpers ---------------------------------------------------
__device__ __forceinline__ uint32_t smem_u32(const void* p) {
    return (uint32_t)__cvta_generic_to_shared(p);
}
__device__ __forceinline__ void cp16(void* s, const void* g) {
    asm volatile("cp.async.ca.shared.global [%0], [%1], 16;\n"
                 :: "r"(smem_u32(s)), "l"(g));
}
__device__ __forceinline__ void cp_commit() { asm volatile("cp.async.commit_group;\n"); }
template <int N>
__device__ __forceinline__ void cp_wait() { asm volatile("cp.async.wait_group %0;\n" :: "n"(N)); }

__device__ __forceinline__ void ldm_x4(uint32_t* r, uint32_t addr) {
    asm volatile("ldmatrix.sync.aligned.m8n8.x4.shared.b16 {%0,%1,%2,%3}, [%4];"
                 : "=r"(r[0]), "=r"(r[1]), "=r"(r[2]), "=r"(r[3]) : "r"(addr));
}
__device__ __forceinline__ void mma16816(float* d, const uint32_t* a, const uint32_t* b) {
    asm volatile(
        "mma.sync.aligned.m16n8k16.row.col.f32.f16.f16.f32 "
        "{%0,%1,%2,%3},{%4,%5,%6,%7},{%8,%9},{%0,%1,%2,%3};"
        : "+f"(d[0]), "+f"(d[1]), "+f"(d[2]), "+f"(d[3])
        : "r"(a[0]), "r"(a[1]), "r"(a[2]), "r"(a[3]), "r"(b[0]), "r"(b[1]));
}

__device__ __forceinline__ void split1(float v, h16& h, h16& l) {
    h = __float2half_rn(v);
    l = __float2half_rn(v - __half2float(h));
}
__device__ __forceinline__ uint32_t pk2(h16 a, h16 b) {
    return (uint32_t)__half_as_ushort(a) | ((uint32_t)__half_as_ushort(b) << 16);
}

// ---------------- split / fused prep kernels ---------------------------------
__global__ __launch_bounds__(256) void split_kernel(
    const float4* __restrict__ in, uint2* __restrict__ h, uint2* __restrict__ l)
{
    int i = blockIdx.x * 256 + threadIdx.x;
    float4 v = in[i];
    h16 h0, l0, h1, l1, h2, l2, h3, l3;
    split1(v.x, h0, l0); split1(v.y, h1, l1); split1(v.z, h2, l2); split1(v.w, h3, l3);
    h[i] = make_uint2(pk2(h0, h1), pk2(h2, h3));
    l[i] = make_uint2(pk2(l0, l1), pk2(l2, l3));
}

// X prep: one block per row. Split X -> Xh/Xl and base[row] = X·Ws1 + bs.
__global__ __launch_bounds__(256) void xprep_kernel(
    const float4* __restrict__ X, const float4* __restrict__ ws1,
    const float* __restrict__ bs,
    uint2* __restrict__ Xh, uint2* __restrict__ Xl, float* __restrict__ base)
{
    const int row = blockIdx.x, t = threadIdx.x;
    const int i = row * 256 + t;
    float4 v = X[i];
    h16 h0, l0, h1, l1, h2, l2, h3, l3;
    split1(v.x, h0, l0); split1(v.y, h1, l1); split1(v.z, h2, l2); split1(v.w, h3, l3);
    Xh[i] = make_uint2(pk2(h0, h1), pk2(h2, h3));
    Xl[i] = make_uint2(pk2(l0, l1), pk2(l2, l3));

    float4 w = ws1[t];
    float s = v.x * w.x + v.y * w.y + v.z * w.z + v.w * w.w;
    __shared__ float red[8];
    #pragma unroll
    for (int o = 16; o; o >>= 1) s += __shfl_xor_sync(0xffffffffu, s, o);
    if ((t & 31) == 0) red[t >> 5] = s;
    __syncthreads();
    if (t == 0) {
        float r = 0.f;
        #pragma unroll
        for (int k = 0; k < 8; k++) r += red[k];
        base[row] = r + bs[0];
    }
}

// Y prep: one block per (b,t) row. Split Y -> Yh/Yl; split(Y*ws3) -> W2 bottom row
// (high limb only — G GEMM is 1-phase and never reads the low limb);
// c[row] = Y·wc; z[row] = Y·Ws2.
__global__ __launch_bounds__(256) void yprep_kernel(
    const float4* __restrict__ Y, const float4* __restrict__ Ws,
    const float4* __restrict__ wc,
    uint2* __restrict__ Yh, uint2* __restrict__ Yl,
    uint2* __restrict__ W2h,
    float* __restrict__ cb, float* __restrict__ zb)
{
    const int row = blockIdx.x, t = threadIdx.x;     // row in [0, 8192)
    const int b = row >> 9, tt = row & 511;
    const int i = row * 256 + t;
    float4 v = Y[i];
    h16 h0, l0, h1, l1, h2, l2, h3, l3;
    split1(v.x, h0, l0); split1(v.y, h1, l1); split1(v.z, h2, l2); split1(v.w, h3, l3);
    Yh[i] = make_uint2(pk2(h0, h1), pk2(h2, h3));
    Yl[i] = make_uint2(pk2(l0, l1), pk2(l2, l3));

    float4 w3 = Ws[512 + t];                          // ws3 = Ws + 2048 floats
    h16 g0 = __float2half_rn(v.x * w3.x), g1 = __float2half_rn(v.y * w3.y);
    h16 g2 = __float2half_rn(v.z * w3.z), g3 = __float2half_rn(v.w * w3.w);
    const int o = (b * 1024 + 512 + tt) * 256 + t;    // W2 bottom row, uint2 units
    W2h[o] = make_uint2(pk2(g0, g1), pk2(g2, g3));

    float4 u = wc[t];
    float4 w2 = Ws[256 + t];                          // ws2 = Ws + 1024 floats
    float s1 = v.x * u.x + v.y * u.y + v.z * u.z + v.w * u.w;
    float s2 = v.x * w2.x + v.y * w2.y + v.z * w2.z + v.w * w2.w;
    __shared__ float r1[8], r2[8];
    #pragma unroll
    for (int o2 = 16; o2; o2 >>= 1) {
        s1 += __shfl_xor_sync(0xffffffffu, s1, o2);
        s2 += __shfl_xor_sync(0xffffffffu, s2, o2);
    }
    if ((t & 31) == 0) { r1[t >> 5] = s1; r2[t >> 5] = s2; }
    __syncthreads();
    if (t == 0) {
        float a1 = 0.f, a2 = 0.f;
        #pragma unroll
        for (int k = 0; k < 8; k++) { a1 += r1[k]; a2 += r2[k]; }
        cb[row] = a1; zb[row] = a2;
    }
}

// reduce 4 split-K fp32 partials of M and split to h/l
__global__ __launch_bounds__(256) void reduce_split_kernel(
    const float4* __restrict__ part, uint2* __restrict__ h, uint2* __restrict__ l)
{
    int i = blockIdx.x * 256 + threadIdx.x;
    const int S = DD * DD / 4;
    float4 a = part[i], b = part[i + S], c = part[i + 2 * S], d = part[i + 3 * S];
    float4 v = make_float4(a.x + b.x + c.x + d.x, a.y + b.y + c.y + d.y,
                           a.z + b.z + c.z + d.z, a.w + b.w + c.w + d.w);
    h16 h0, l0, h1, l1, h2, l2, h3, l3;
    split1(v.x, h0, l0); split1(v.y, h1, l1); split1(v.z, h2, l2); split1(v.w, h3, l3);
    h[i] = make_uint2(pk2(h0, h1), pk2(h2, h3));
    l[i] = make_uint2(pk2(l0, l1), pk2(l2, l3));
}

// ---------------- fp16 split NT GEMM (R3/R8-proven inner loop) ---------------
// C[m,n] = sum over NPH phases: (0) Ah*Bh, (1) Al*Bh, (2) Ah*Bl. K per phase, row stride ld.
// EPI=0: fp32 store. EPI=1: split-store h16 into Ch/Cl.
template <int EPI, int NPH>
__global__ __launch_bounds__(256, 2) void gemm_h16_nt(
    const h16* __restrict__ Ah, const h16* __restrict__ Al,
    const h16* __restrict__ Bh, const h16* __restrict__ Bl,
    float* __restrict__ C, h16* __restrict__ Ch, h16* __restrict__ Cl,
    int K, int ld, int ldc, long long sA, long long sB, long long sC)
{
    const int bz = blockIdx.z;
    Ah += bz * sA; Al += bz * sA; Bh += bz * sB; Bl += bz * sB;

    const int m0 = blockIdx.y * 128, n0 = blockIdx.x * 128;
    const int tid = threadIdx.x, lane = tid & 31, wid = tid >> 5;
    const int wm = (wid & 1) * 64, wn = (wid >> 1) * 32;

    __shared__ h16 sm[2][2][128 * 40];

    float acc[4][4][4];
    #pragma unroll
    for (int i = 0; i < 4; i++)
        #pragma unroll
        for (int j = 0; j < 4; j++)
            #pragma unroll
            for (int q = 0; q < 4; q++) acc[i][j][q] = 0.f;

    const int ar0 = tid >> 2,          ak0 = (tid & 3) * 8;
    const int ar1 = (tid + 256) >> 2,  ak1 = ((tid + 256) & 3) * 8;

    const int nch = (NPH * K) / 32;

    auto issue = [&](int chunk, int stage) {
        int kk = chunk * 32;
        int phase = kk / K, kin = kk - phase * K;
        const h16* pA = (phase == 1) ? Al : Ah;
        const h16* pB = (phase == 2) ? Bl : Bh;
        cp16(&sm[stage][0][ar0 * 40 + ak0], pA + (long long)(m0 + ar0) * ld + kin + ak0);
        cp16(&sm[stage][0][ar1 * 40 + ak1], pA + (long long)(m0 + ar1) * ld + kin + ak1);
        cp16(&sm[stage][1][ar0 * 40 + ak0], pB + (long long)(n0 + ar0) * ld + kin + ak0);
        cp16(&sm[stage][1][ar1 * 40 + ak1], pB + (long long)(n0 + ar1) * ld + kin + ak1);
        cp_commit();
    };

    issue(0, 0);

    const int aRow = lane & 15, aKof = (lane >> 4) * 8;
    const int bRow = ((lane >> 4) << 3) + (lane & 7), bKof = ((lane >> 3) & 1) * 8;

    for (int c = 0; c < nch; c++) {
        int st = c & 1;
        if (c + 1 < nch) { issue(c + 1, st ^ 1); cp_wait<1>(); }
        else             { cp_wait<0>(); }
        __syncthreads();

        #pragma unroll
        for (int ks = 0; ks < 32; ks += 16) {
            uint32_t af[4][4];
            #pragma unroll
            for (int mt = 0; mt < 4; mt++)
                ldm_x4(af[mt], smem_u32(&sm[st][0][(wm + mt * 16 + aRow) * 40 + ks + aKof]));
            uint32_t bfr[2][4];
            #pragma unroll
            for (int bt = 0; bt < 2; bt++)
                ldm_x4(bfr[bt], smem_u32(&sm[st][1][(wn + bt * 16 + bRow) * 40 + ks + bKof]));
            #pragma unroll
            for (int mt = 0; mt < 4; mt++) {
                #pragma unroll
                for (int nt = 0; nt < 4; nt++) {
                    mma16816(acc[mt][nt], af[mt], &bfr[nt >> 1][(nt & 1) * 2]);
                }
            }
        }
        __syncthreads();
    }

    // epilogue
    const int tg = lane >> 2, tl = lane & 3;
    #pragma unroll
    for (int mt = 0; mt < 4; mt++) {
        #pragma unroll
        for (int nt = 0; nt < 4; nt++) {
            int m = m0 + wm + mt * 16 + tg;
            int n = n0 + wn + nt * 8 + 2 * tl;
            float v0 = acc[mt][nt][0], v1 = acc[mt][nt][1];
            float v2 = acc[mt][nt][2], v3 = acc[mt][nt][3];
            if (EPI == 0) {
                float* Cb = C + bz * sC;
                *reinterpret_cast<float2*>(&Cb[(long long)m * ldc + n])       = make_float2(v0, v1);
                *reinterpret_cast<float2*>(&Cb[(long long)(m + 8) * ldc + n]) = make_float2(v2, v3);
            } else {
                h16 h0,l0,h1,l1,h2,l2,h3,l3;
                split1(v0, h0, l0); split1(v1, h1, l1); split1(v2, h2, l2); split1(v3, h3, l3);
                h16* Hb = Ch + bz * sC; h16* Lb = Cl + bz * sC;
                *reinterpret_cast<uint32_t*>(&Hb[(long long)m * ldc + n])       = pk2(h0, h1);
                *reinterpret_cast<uint32_t*>(&Lb[(long long)m * ldc + n])       = pk2(l0, l1);
                *reinterpret_cast<uint32_t*>(&Hb[(long long)(m + 8) * ldc + n]) = pk2(h2, h3);
                *reinterpret_cast<uint32_t*>(&Lb[(long long)(m + 8) * ldc + n]) = pk2(l2, l3);
            }
        }
    }
}

// ---------------- aux kernels (fp32) ----------------------------------------
__global__ __launch_bounds__(256) void rowdot_kernel(
    const float* __restrict__ A, const float* __restrict__ v,
    const float* __restrict__ addp, float* __restrict__ out, int K)
{
    int row = blockIdx.x * 8 + (threadIdx.x >> 5);
    int lane = threadIdx.x & 31;
    const float* a = A + (long long)row * K;
    float s = 0.f;
    for (int i = lane * 4; i < K; i += 128) {
        float4 x = *reinterpret_cast<const float4*>(&a[i]);
        float4 w = *reinterpret_cast<const float4*>(&v[i]);
        s += x.x * w.x + x.y * w.y + x.z * w.z + x.w * w.w;
    }
    #pragma unroll
    for (int o = 16; o; o >>= 1) s += __shfl_xor_sync(0xffffffffu, s, o);
    if (lane == 0) out[row] = s + (addp ? addp[0] : 0.f);
}

__global__ __launch_bounds__(256) void softmax_out_kernel(
    const float* __restrict__ P, const float* __restrict__ c,
    const float* __restrict__ z, const float* __restrict__ base,
    float* __restrict__ out)
{
    const int b = blockIdx.y, r = blockIdx.x;
    const float* Prow = P + ((long long)b * RR + r) * (2 * TT);
    const float* cbp = c + b * TT;
    const float* zbp = z + b * TT;
    const int t = threadIdx.x;
    const int lane = t & 31, wid = t >> 5;

    float s0 = Prow[t]       + cbp[t];
    float s1 = Prow[t + 256] + cbp[t + 256];
    float g0 = Prow[512 + t];
    float g1 = Prow[768 + t];

    __shared__ float sm[8], smp[8], smw[8];

    float m = fmaxf(s0, s1);
    #pragma unroll
    for (int o = 16; o; o >>= 1) m = fmaxf(m, __shfl_xor_sync(0xffffffffu, m, o));
    if (lane == 0) sm[wid] = m;
    __syncthreads();
    if (wid == 0) {
        float v = sm[lane & 7];
        #pragma unroll
        for (int o = 4; o; o >>= 1) v = fmaxf(v, __shfl_xor_sync(0xffffffffu, v, o));
        if (lane == 0) sm[0] = v;
    }
    __syncthreads();
    m = sm[0];

    float p0 = expf(s0 - m), p1 = expf(s1 - m);
    float ps = p0 + p1;
    float ws = p0 * (zbp[t] + g0) + p1 * (zbp[t + 256] + g1);
    #pragma unroll
    for (int o = 16; o; o >>= 1) {
        ps += __shfl_xor_sync(0xffffffffu, ps, o);
        ws += __shfl_xor_sync(0xffffffffu, ws, o);
    }
    if (lane == 0) { smp[wid] = ps; smw[wid] = ws; }
    __syncthreads();
    if (t == 0) {
        float tp = 0.f, tw = 0.f;
        #pragma unroll
        for (int i = 0; i < 8; i++) { tp += smp[i]; tw += smw[i]; }
        out[b * RR + r] = base[b * RR + r] + tw / tp;
    }
}

// ---------------- launch ----------------------------------------------------
extern "C" void kernel_launch(void* const* d_in, const int* in_sizes, int n_in,
                              void* d_out, int out_size)
{
    const float* X  = (const float*)d_in[0]; // [B,R,D]
    const float* Y  = (const float*)d_in[1]; // [B,T,D]
    const float* Wr = (const float*)d_in[2]; // [D,H]
    const float* br = (const float*)d_in[3]; // [H]
    const float* Wq = (const float*)d_in[4]; // [D,H]
    const float* bq = (const float*)d_in[5]; // [H] (enters only via softmax-invariant terms)
    const float* Ws = (const float*)d_in[6]; // [3D]
    const float* bs = (const float*)d_in[7]; // [1]
    float* out = (float*)d_out;
    (void)bq;

    float *P, *cb, *zb, *baseb, *wc;
    h16 *Xh, *Xl, *Yh, *Yl, *Wrh, *Wrl, *Wqh, *Wql, *Mh, *Ml, *W2h, *W2l;
    cudaGetSymbolAddress((void**)&P, g_P);
    cudaGetSymbolAddress((void**)&cb, g_c);
    cudaGetSymbolAddress((void**)&zb, g_z);
    cudaGetSymbolAddress((void**)&baseb, g_base);
    cudaGetSymbolAddress((void**)&wc, g_wc);
    cudaGetSymbolAddress((void**)&Xh, g_Xh);   cudaGetSymbolAddress((void**)&Xl, g_Xl);
    cudaGetSymbolAddress((void**)&Yh, g_Yh);   cudaGetSymbolAddress((void**)&Yl, g_Yl);
    cudaGetSymbolAddress((void**)&Wrh, g_Wrh); cudaGetSymbolAddress((void**)&Wrl, g_Wrl);
    cudaGetSymbolAddress((void**)&Wqh, g_Wqh); cudaGetSymbolAddress((void**)&Wql, g_Wql);
    cudaGetSymbolAddress((void**)&Mh, g_Mh);   cudaGetSymbolAddress((void**)&Ml, g_Ml);
    cudaGetSymbolAddress((void**)&W2h, g_W2h); cudaGetSymbolAddress((void**)&W2l, g_W2l);

    // weight splits
    split_kernel<<<DD * HH / 1024, 256>>>((const float4*)Wr, (uint2*)Wrh, (uint2*)Wrl);
    split_kernel<<<DD * HH / 1024, 256>>>((const float4*)Wq, (uint2*)Wqh, (uint2*)Wql);

    // M = Wr @ Wq^T (contraction over h): split-K x4 (k-offset 256 per bz) into g_P
    // scratch, then reduce + split to h/l.
    gemm_h16_nt<0, 3><<<dim3(8, 8, 4), 256>>>(
        Wrh, Wrl, Wqh, Wql, P, nullptr, nullptr,
        256, HH, DD, 256LL, 256LL, (long long)DD * DD);
    reduce_split_kernel<<<DD * DD / 1024, 256>>>((const float4*)P, (uint2*)Mh, (uint2*)Ml);

    // wc = Wq @ br (exact fp32)
    rowdot_kernel<<<DD / 8, 256>>>(Wq, br, nullptr, wc, HH);

    // fused prep: X split + base; Y split + W2 bottom (high limb) + c/z
    xprep_kernel<<<BB * RR, 256>>>((const float4*)X, (const float4*)Ws, bs,
                                   (uint2*)Xh, (uint2*)Xl, baseb);
    yprep_kernel<<<BB * TT, 256>>>((const float4*)Y, (const float4*)Ws, (const float4*)wc,
                                   (uint2*)Yh, (uint2*)Yl, (uint2*)W2h, cb, zb);

    // V = Y @ M^T -> split-stored into W2 rows [0,512)  (per batch M=512, N=1024), 3-phase
    gemm_h16_nt<1, 3><<<dim3(8, 4, BB), 256>>>(
        Yh, Yl, Mh, Ml, nullptr, W2h, W2l,
        DD, DD, DD, (long long)TT * DD, 0LL, (long long)2 * TT * DD);

    // P (S half) = X @ V^T : cols [0,512), 3-phase
    gemm_h16_nt<0, 3><<<dim3(4, 8, BB), 256>>>(
        Xh, Xl, W2h, W2l, P, nullptr, nullptr,
        DD, DD, 2 * TT, (long long)RR * DD, (long long)2 * TT * DD, (long long)RR * 2 * TT);

    // P (G half) = X @ Yw^T : cols [512,1024), 1-phase (hh only)
    gemm_h16_nt<0, 1><<<dim3(4, 8, BB), 256>>>(
        Xh, Xl, W2h + (long long)512 * DD, nullptr, P + 512, nullptr, nullptr,
        DD, DD, 2 * TT, (long long)RR * DD, (long long)2 * TT * DD, (long long)RR * 2 * TT);

    // softmax + fused epilogue
    softmax_out_kernel<<<dim3(RR, BB), 256>>>(P, cb, zb, baseb, out);
}

// round 11
// speedup vs baseline: 1.8487x; 1.0531x over previous
#include <cuda_runtime.h>
#include <cuda_fp16.h>
#include <cstdint>

// Problem constants
#define BB 16
#define RR 1024
#define TT 512
#define DD 1024
#define HH 1024

typedef __half h16;

// ---------------- scratch (__device__ globals; no allocation allowed) -------
__device__ float g_P [BB * RR * TT];          // 32 MB: S scores (ld 512); head reused as M split-K scratch
__device__ h16   g_G [BB * RR * TT];          // 16 MB: G half (fp16, ld 512)
__device__ h16   g_Xh[BB * RR * DD], g_Xl[BB * RR * DD];
__device__ h16   g_Yh[BB * TT * DD], g_Yl[BB * TT * DD];
__device__ h16   g_Wrh[DD * HH], g_Wrl[DD * HH];
__device__ h16   g_Wqh[DD * HH], g_Wql[DD * HH];
__device__ h16   g_Mh[DD * DD], g_Ml[DD * DD];
__device__ h16   g_W2h[BB * 2 * TT * DD], g_W2l[BB * 2 * TT * DD];
__device__ float g_Mscr[4 * DD * DD];         // 16 MB: M split-K partials
__device__ float g_c[BB * TT], g_z[BB * TT], g_base[BB * RR];
__device__ float g_wc[DD];

// ---------------- fork/join resources (host-side, created pre-main) ---------
struct HostRes {
    cudaStream_t sB;
    cudaEvent_t evRoot, evY, evX, evB;
    HostRes() {
        cudaStreamCreateWithFlags(&sB, cudaStreamNonBlocking);
        cudaEventCreateWithFlags(&evRoot, cudaEventDisableTiming);
        cudaEventCreateWithFlags(&evY,   cudaEventDisableTiming);
        cudaEventCreateWithFlags(&evX,   cudaEventDisableTiming);
        cudaEventCreateWithFlags(&evB,   cudaEventDisableTiming);
    }
};
static HostRes g_res;

// ---------------- helpers ---------------------------------------------------
__device__ __forceinline__ uint32_t smem_u32(const void* p) {
    return (uint32_t)__cvta_generic_to_shared(p);
}
__device__ __forceinline__ void cp16(void* s, const void* g) {
    asm volatile("cp.async.ca.shared.global [%0], [%1], 16;\n"
                 :: "r"(smem_u32(s)), "l"(g));
}
__device__ __forceinline__ void cp_commit() { asm volatile("cp.async.commit_group;\n"); }
template <int N>
__device__ __forceinline__ void cp_wait() { asm volatile("cp.async.wait_group %0;\n" :: "n"(N)); }

__device__ __forceinline__ void ldm_x4(uint32_t* r, uint32_t addr) {
    asm volatile("ldmatrix.sync.aligned.m8n8.x4.shared.b16 {%0,%1,%2,%3}, [%4];"
                 : "=r"(r[0]), "=r"(r[1]), "=r"(r[2]), "=r"(r[3]) : "r"(addr));
}
__device__ __forceinline__ void mma16816(float* d, const uint32_t* a, const uint32_t* b) {
    asm volatile(
        "mma.sync.aligned.m16n8k16.row.col.f32.f16.f16.f32 "
        "{%0,%1,%2,%3},{%4,%5,%6,%7},{%8,%9},{%0,%1,%2,%3};"
        : "+f"(d[0]), "+f"(d[1]), "+f"(d[2]), "+f"(d[3])
        : "r"(a[0]), "r"(a[1]), "r"(a[2]), "r"(a[3]), "r"(b[0]), "r"(b[1]));
}

__device__ __forceinline__ void split1(float v, h16& h, h16& l) {
    h = __float2half_rn(v);
    l = __float2half_rn(v - __half2float(h));
}
__device__ __forceinline__ uint32_t pk2(h16 a, h16 b) {
    return (uint32_t)__half_as_ushort(a) | ((uint32_t)__half_as_ushort(b) << 16);
}

// ---------------- split / fused prep kernels ---------------------------------
__global__ __launch_bounds__(256) void split_kernel(
    const float4* __restrict__ in, uint2* __restrict__ h, uint2* __restrict__ l)
{
    int i = blockIdx.x * 256 + threadIdx.x;
    float4 v = in[i];
    h16 h0, l0, h1, l1, h2, l2, h3, l3;
    split1(v.x, h0, l0); split1(v.y, h1, l1); split1(v.z, h2, l2); split1(v.w, h3, l3);
    h[i] = make_uint2(pk2(h0, h1), pk2(h2, h3));
    l[i] = make_uint2(pk2(l0, l1), pk2(l2, l3));
}

// X prep: one block per row. Split X -> Xh/Xl and base[row] = X·Ws1 + bs.
__global__ __launch_bounds__(256) void xprep_kernel(
    const float4* __restrict__ X, const float4* __restrict__ ws1,
    const float* __restrict__ bs,
    uint2* __restrict__ Xh, uint2* __restrict__ Xl, float* __restrict__ base)
{
    const int row = blockIdx.x, t = threadIdx.x;
    const int i = row * 256 + t;
    float4 v = X[i];
    h16 h0, l0, h1, l1, h2, l2, h3, l3;
    split1(v.x, h0, l0); split1(v.y, h1, l1); split1(v.z, h2, l2); split1(v.w, h3, l3);
    Xh[i] = make_uint2(pk2(h0, h1), pk2(h2, h3));
    Xl[i] = make_uint2(pk2(l0, l1), pk2(l2, l3));

    float4 w = ws1[t];
    float s = v.x * w.x + v.y * w.y + v.z * w.z + v.w * w.w;
    __shared__ float red[8];
    #pragma unroll
    for (int o = 16; o; o >>= 1) s += __shfl_xor_sync(0xffffffffu, s, o);
    if ((t & 31) == 0) red[t >> 5] = s;
    __syncthreads();
    if (t == 0) {
        float r = 0.f;
        #pragma unroll
        for (int k = 0; k < 8; k++) r += red[k];
        base[row] = r + bs[0];
    }
}

// Y prep: one block per (b,t) row. Split Y -> Yh/Yl; fp16(Y*ws3) -> W2 bottom row
// (high limb only — G GEMM is 1-phase); c[row] = Y·wc; z[row] = Y·Ws2.
__global__ __launch_bounds__(256) void yprep_kernel(
    const float4* __restrict__ Y, const float4* __restrict__ Ws,
    const float4* __restrict__ wc,
    uint2* __restrict__ Yh, uint2* __restrict__ Yl,
    uint2* __restrict__ W2h,
    float* __restrict__ cb, float* __restrict__ zb)
{
    const int row = blockIdx.x, t = threadIdx.x;     // row in [0, 8192)
    const int b = row >> 9, tt = row & 511;
    const int i = row * 256 + t;
    float4 v = Y[i];
    h16 h0, l0, h1, l1, h2, l2, h3, l3;
    split1(v.x, h0, l0); split1(v.y, h1, l1); split1(v.z, h2, l2); split1(v.w, h3, l3);
    Yh[i] = make_uint2(pk2(h0, h1), pk2(h2, h3));
    Yl[i] = make_uint2(pk2(l0, l1), pk2(l2, l3));

    float4 w3 = Ws[512 + t];                          // ws3 = Ws + 2048 floats
    h16 g0 = __float2half_rn(v.x * w3.x), g1 = __float2half_rn(v.y * w3.y);
    h16 g2 = __float2half_rn(v.z * w3.z), g3 = __float2half_rn(v.w * w3.w);
    const int o = (b * 1024 + 512 + tt) * 256 + t;    // W2 bottom row, uint2 units
    W2h[o] = make_uint2(pk2(g0, g1), pk2(g2, g3));

    float4 u = wc[t];
    float4 w2 = Ws[256 + t];                          // ws2 = Ws + 1024 floats
    float s1 = v.x * u.x + v.y * u.y + v.z * u.z + v.w * u.w;
    float s2 = v.x * w2.x + v.y * w2.y + v.z * w2.z + v.w * w2.w;
    __shared__ float r1[8], r2[8];
    #pragma unroll
    for (int o2 = 16; o2; o2 >>= 1) {
        s1 += __shfl_xor_sync(0xffffffffu, s1, o2);
        s2 += __shfl_xor_sync(0xffffffffu, s2, o2);
    }
    if ((t & 31) == 0) { r1[t >> 5] = s1; r2[t >> 5] = s2; }
    __syncthreads();
    if (t == 0) {
        float a1 = 0.f, a2 = 0.f;
        #pragma unroll
        for (int k = 0; k < 8; k++) { a1 += r1[k]; a2 += r2[k]; }
        cb[row] = a1; zb[row] = a2;
    }
}

// reduce 4 split-K fp32 partials of M and split to h/l
__global__ __launch_bounds__(256) void reduce_split_kernel(
    const float4* __restrict__ part, uint2* __restrict__ h, uint2* __restrict__ l)
{
    int i = blockIdx.x * 256 + threadIdx.x;
    const int S = DD * DD / 4;
    float4 a = part[i], b = part[i + S], c = part[i + 2 * S], d = part[i + 3 * S];
    float4 v = make_float4(a.x + b.x + c.x + d.x, a.y + b.y + c.y + d.y,
                           a.z + b.z + c.z + d.z, a.w + b.w + c.w + d.w);
    h16 h0, l0, h1, l1, h2, l2, h3, l3;
    split1(v.x, h0, l0); split1(v.y, h1, l1); split1(v.z, h2, l2); split1(v.w, h3, l3);
    h[i] = make_uint2(pk2(h0, h1), pk2(h2, h3));
    l[i] = make_uint2(pk2(l0, l1), pk2(l2, l3));
}

// ---------------- fp16 split NT GEMM (R3/R8-proven inner loop) ---------------
// C[m,n] = sum over NPH phases: (0) Ah*Bh, (1) Al*Bh, (2) Ah*Bl. K per phase, row stride ld.
// EPI=0: fp32 store to C. EPI=1: split-store h16 into Ch/Cl. EPI=2: fp16 store to Ch.
template <int EPI, int NPH>
__global__ __launch_bounds__(256, 2) void gemm_h16_nt(
    const h16* __restrict__ Ah, const h16* __restrict__ Al,
    const h16* __restrict__ Bh, const h16* __restrict__ Bl,
    float* __restrict__ C, h16* __restrict__ Ch, h16* __restrict__ Cl,
    int K, int ld, int ldc, long long sA, long long sB, long long sC)
{
    const int bz = blockIdx.z;
    Ah += bz * sA; Al += bz * sA; Bh += bz * sB; Bl += bz * sB;

    const int m0 = blockIdx.y * 128, n0 = blockIdx.x * 128;
    const int tid = threadIdx.x, lane = tid & 31, wid = tid >> 5;
    const int wm = (wid & 1) * 64, wn = (wid >> 1) * 32;

    __shared__ h16 sm[2][2][128 * 40];

    float acc[4][4][4];
    #pragma unroll
    for (int i = 0; i < 4; i++)
        #pragma unroll
        for (int j = 0; j < 4; j++)
            #pragma unroll
            for (int q = 0; q < 4; q++) acc[i][j][q] = 0.f;

    const int ar0 = tid >> 2,          ak0 = (tid & 3) * 8;
    const int ar1 = (tid + 256) >> 2,  ak1 = ((tid + 256) & 3) * 8;

    const int nch = (NPH * K) / 32;

    auto issue = [&](int chunk, int stage) {
        int kk = chunk * 32;
        int phase = kk / K, kin = kk - phase * K;
        const h16* pA = (phase == 1) ? Al : Ah;
        const h16* pB = (phase == 2) ? Bl : Bh;
        cp16(&sm[stage][0][ar0 * 40 + ak0], pA + (long long)(m0 + ar0) * ld + kin + ak0);
        cp16(&sm[stage][0][ar1 * 40 + ak1], pA + (long long)(m0 + ar1) * ld + kin + ak1);
        cp16(&sm[stage][1][ar0 * 40 + ak0], pB + (long long)(n0 + ar0) * ld + kin + ak0);
        cp16(&sm[stage][1][ar1 * 40 + ak1], pB + (long long)(n0 + ar1) * ld + kin + ak1);
        cp_commit();
    };

    issue(0, 0);

    const int aRow = lane & 15, aKof = (lane >> 4) * 8;
    const int bRow = ((lane >> 4) << 3) + (lane & 7), bKof = ((lane >> 3) & 1) * 8;

    for (int c = 0; c < nch; c++) {
        int st = c & 1;
        if (c + 1 < nch) { issue(c + 1, st ^ 1); cp_wait<1>(); }
        else             { cp_wait<0>(); }
        __syncthreads();

        #pragma unroll
        for (int ks = 0; ks < 32; ks += 16) {
            uint32_t af[4][4];
            #pragma unroll
            for (int mt = 0; mt < 4; mt++)
                ldm_x4(af[mt], smem_u32(&sm[st][0][(wm + mt * 16 + aRow) * 40 + ks + aKof]));
            uint32_t bfr[2][4];
            #pragma unroll
            for (int bt = 0; bt < 2; bt++)
                ldm_x4(bfr[bt], smem_u32(&sm[st][1][(wn + bt * 16 + bRow) * 40 + ks + bKof]));
            #pragma unroll
            for (int mt = 0; mt < 4; mt++) {
                #pragma unroll
                for (int nt = 0; nt < 4; nt++) {
                    mma16816(acc[mt][nt], af[mt], &bfr[nt >> 1][(nt & 1) * 2]);
                }
            }
        }
        __syncthreads();
    }

    // epilogue
    const int tg = lane >> 2, tl = lane & 3;
    #pragma unroll
    for (int mt = 0; mt < 4; mt++) {
        #pragma unroll
        for (int nt = 0; nt < 4; nt++) {
            int m = m0 + wm + mt * 16 + tg;
            int n = n0 + wn + nt * 8 + 2 * tl;
            float v0 = acc[mt][nt][0], v1 = acc[mt][nt][1];
            float v2 = acc[mt][nt][2], v3 = acc[mt][nt][3];
            if (EPI == 0) {
                float* Cb = C + bz * sC;
                *reinterpret_cast<float2*>(&Cb[(long long)m * ldc + n])       = make_float2(v0, v1);
                *reinterpret_cast<float2*>(&Cb[(long long)(m + 8) * ldc + n]) = make_float2(v2, v3);
            } else if (EPI == 1) {
                h16 h0,l0,h1,l1,h2,l2,h3,l3;
                split1(v0, h0, l0); split1(v1, h1, l1); split1(v2, h2, l2); split1(v3, h3, l3);
                h16* Hb = Ch + bz * sC; h16* Lb = Cl + bz * sC;
                *reinterpret_cast<uint32_t*>(&Hb[(long long)m * ldc + n])       = pk2(h0, h1);
                *reinterpret_cast<uint32_t*>(&Lb[(long long)m * ldc + n])       = pk2(l0, l1);
                *reinterpret_cast<uint32_t*>(&Hb[(long long)(m + 8) * ldc + n]) = pk2(h2, h3);
                *reinterpret_cast<uint32_t*>(&Lb[(long long)(m + 8) * ldc + n]) = pk2(l2, l3);
            } else {
                h16* Gb = Ch + bz * sC;
                *reinterpret_cast<uint32_t*>(&Gb[(long long)m * ldc + n]) =
                    pk2(__float2half_rn(v0), __float2half_rn(v1));
                *reinterpret_cast<uint32_t*>(&Gb[(long long)(m + 8) * ldc + n]) =
                    pk2(__float2half_rn(v2), __float2half_rn(v3));
            }
        }
    }
}

// ---------------- aux kernels (fp32) ----------------------------------------
__global__ __launch_bounds__(256) void rowdot_kernel(
    const float* __restrict__ A, const float* __restrict__ v,
    const float* __restrict__ addp, float* __restrict__ out, int K)
{
    int row = blockIdx.x * 8 + (threadIdx.x >> 5);
    int lane = threadIdx.x & 31;
    const float* a = A + (long long)row * K;
    float s = 0.f;
    for (int i = lane * 4; i < K; i += 128) {
        float4 x = *reinterpret_cast<const float4*>(&a[i]);
        float4 w = *reinterpret_cast<const float4*>(&v[i]);
        s += x.x * w.x + x.y * w.y + x.z * w.z + x.w * w.w;
    }
    #pragma unroll
    for (int o = 16; o; o >>= 1) s += __shfl_xor_sync(0xffffffffu, s, o);
    if (lane == 0) out[row] = s + (addp ? addp[0] : 0.f);
}

__global__ __launch_bounds__(256) void softmax_out_kernel(
    const float* __restrict__ S, const h16* __restrict__ G,
    const float* __restrict__ c, const float* __restrict__ z,
    const float* __restrict__ base, float* __restrict__ out)
{
    const int b = blockIdx.y, r = blockIdx.x;
    const float* Srow = S + ((long long)b * RR + r) * TT;
    const h16*   Grow = G + ((long long)b * RR + r) * TT;
    const float* cbp = c + b * TT;
    const float* zbp = z + b * TT;
    const int t = threadIdx.x;
    const int lane = t & 31, wid = t >> 5;

    float s0 = Srow[t]       + cbp[t];
    float s1 = Srow[t + 256] + cbp[t + 256];
    float g0 = __half2float(Grow[t]);
    float g1 = __half2float(Grow[t + 256]);

    __shared__ float sm[8], smp[8], smw[8];

    float m = fmaxf(s0, s1);
    #pragma unroll
    for (int o = 16; o; o >>= 1) m = fmaxf(m, __shfl_xor_sync(0xffffffffu, m, o));
    if (lane == 0) sm[wid] = m;
    __syncthreads();
    if (wid == 0) {
        float v = sm[lane & 7];
        #pragma unroll
        for (int o = 4; o; o >>= 1) v = fmaxf(v, __shfl_xor_sync(0xffffffffu, v, o));
        if (lane == 0) sm[0] = v;
    }
    __syncthreads();
    m = sm[0];

    float p0 = expf(s0 - m), p1 = expf(s1 - m);
    float ps = p0 + p1;
    float ws = p0 * (zbp[t] + g0) + p1 * (zbp[t + 256] + g1);
    #pragma unroll
    for (int o = 16; o; o >>= 1) {
        ps += __shfl_xor_sync(0xffffffffu, ps, o);
        ws += __shfl_xor_sync(0xffffffffu, ws, o);
    }
    if (lane == 0) { smp[wid] = ps; smw[wid] = ws; }
    __syncthreads();
    if (t == 0) {
        float tp = 0.f, tw = 0.f;
        #pragma unroll
        for (int i = 0; i < 8; i++) { tp += smp[i]; tw += smw[i]; }
        out[b * RR + r] = base[b * RR + r] + tw / tp;
    }
}

// ---------------- launch ----------------------------------------------------
extern "C" void kernel_launch(void* const* d_in, const int* in_sizes, int n_in,
                              void* d_out, int out_size)
{
    const float* X  = (const float*)d_in[0]; // [B,R,D]
    const float* Y  = (const float*)d_in[1]; // [B,T,D]
    const float* Wr = (const float*)d_in[2]; // [D,H]
    const float* br = (const float*)d_in[3]; // [H]
    const float* Wq = (const float*)d_in[4]; // [D,H]
    const float* bq = (const float*)d_in[5]; // [H] (enters only via softmax-invariant terms)
    const float* Ws = (const float*)d_in[6]; // [3D]
    const float* bs = (const float*)d_in[7]; // [1]
    float* out = (float*)d_out;
    (void)bq;

    float *P, *Mscr, *cb, *zb, *baseb, *wc;
    h16 *G, *Xh, *Xl, *Yh, *Yl, *Wrh, *Wrl, *Wqh, *Wql, *Mh, *Ml, *W2h, *W2l;
    cudaGetSymbolAddress((void**)&P, g_P);
    cudaGetSymbolAddress((void**)&G, g_G);
    cudaGetSymbolAddress((void**)&Mscr, g_Mscr);
    cudaGetSymbolAddress((void**)&cb, g_c);
    cudaGetSymbolAddress((void**)&zb, g_z);
    cudaGetSymbolAddress((void**)&baseb, g_base);
    cudaGetSymbolAddress((void**)&wc, g_wc);
    cudaGetSymbolAddress((void**)&Xh, g_Xh);   cudaGetSymbolAddress((void**)&Xl, g_Xl);
    cudaGetSymbolAddress((void**)&Yh, g_Yh);   cudaGetSymbolAddress((void**)&Yl, g_Yl);
    cudaGetSymbolAddress((void**)&Wrh, g_Wrh); cudaGetSymbolAddress((void**)&Wrl, g_Wrl);
    cudaGetSymbolAddress((void**)&Wqh, g_Wqh); cudaGetSymbolAddress((void**)&Wql, g_Wql);
    cudaGetSymbolAddress((void**)&Mh, g_Mh);   cudaGetSymbolAddress((void**)&Ml, g_Ml);
    cudaGetSymbolAddress((void**)&W2h, g_W2h); cudaGetSymbolAddress((void**)&W2l, g_W2l);

    cudaStream_t sB = g_res.sB;

    // ---- fork: bring side stream into the (possibly capturing) main stream ----
    cudaEventRecord(g_res.evRoot, 0);
    cudaStreamWaitEvent(sB, g_res.evRoot, 0);

    // ---- side stream B: wc -> yprep -> [evY] -> xprep -> [evX] -> G GEMM -> [evB]
    rowdot_kernel<<<DD / 8, 256, 0, sB>>>(Wq, br, nullptr, wc, HH);
    yprep_kernel<<<BB * TT, 256, 0, sB>>>((const float4*)Y, (const float4*)Ws, (const float4*)wc,
                                          (uint2*)Yh, (uint2*)Yl, (uint2*)W2h, cb, zb);
    cudaEventRecord(g_res.evY, sB);
    xprep_kernel<<<BB * RR, 256, 0, sB>>>((const float4*)X, (const float4*)Ws, bs,
                                          (uint2*)Xh, (uint2*)Xl, baseb);
    cudaEventRecord(g_res.evX, sB);
    // G = X @ Yw^T  (fp16 out, 1-phase) — backfills V/S wave gaps on the main stream
    gemm_h16_nt<2, 1><<<dim3(4, 8, BB), 256, 0, sB>>>(
        Xh, nullptr, W2h + (long long)512 * DD, nullptr, nullptr, G, nullptr,
        DD, DD, TT, (long long)RR * DD, (long long)2 * TT * DD, (long long)RR * TT);
    cudaEventRecord(g_res.evB, sB);

    // ---- main stream: weight splits -> M -> reduce -> V -> S ----
    split_kernel<<<DD * HH / 1024, 256>>>((const float4*)Wr, (uint2*)Wrh, (uint2*)Wrl);
    split_kernel<<<DD * HH / 1024, 256>>>((const float4*)Wq, (uint2*)Wqh, (uint2*)Wql);

    // M = Wr @ Wq^T: split-K x4 (k-offset 256 per bz) into scratch, then reduce+split.
    gemm_h16_nt<0, 3><<<dim3(8, 8, 4), 256>>>(
        Wrh, Wrl, Wqh, Wql, Mscr, nullptr, nullptr,
        256, HH, DD, 256LL, 256LL, (long long)DD * DD);
    reduce_split_kernel<<<DD * DD / 1024, 256>>>((const float4*)Mscr, (uint2*)Mh, (uint2*)Ml);

    // V = Y @ M^T -> split-stored into W2 rows [0,512) (needs yprep)
    cudaStreamWaitEvent(0, g_res.evY, 0);
    gemm_h16_nt<1, 3><<<dim3(8, 4, BB), 256>>>(
        Yh, Yl, Mh, Ml, nullptr, W2h, W2l,
        DD, DD, DD, (long long)TT * DD, 0LL, (long long)2 * TT * DD);

    // S = X @ V^T (fp32, ld 512; needs xprep)
    cudaStreamWaitEvent(0, g_res.evX, 0);
    gemm_h16_nt<0, 3><<<dim3(4, 8, BB), 256>>>(
        Xh, Xl, W2h, W2l, P, nullptr, nullptr,
        DD, DD, TT, (long long)RR * DD, (long long)2 * TT * DD, (long long)RR * TT);

    // ---- join side stream, then softmax + fused epilogue ----
    cudaStreamWaitEvent(0, g_res.evB, 0);
    softmax_out_kernel<<<dim3(RR, BB), 256>>>(P, G, cb, zb, baseb, out);
}

// round 12
// speedup vs baseline: 1.8737x; 1.0135x over previous
#include <cuda_runtime.h>
#include <cuda_fp16.h>
#include <cstdint>

// Problem constants
#define BB 16
#define RR 1024
#define TT 512
#define DD 1024
#define HH 1024

typedef __half h16;

// ---------------- scratch (__device__ globals; no allocation allowed) -------
__device__ float g_P [BB * RR * TT];          // 32 MB: S scores (ld 512)
__device__ h16   g_G [BB * RR * TT];          // 16 MB: G half (fp16, ld 512)
__device__ h16   g_Xh[BB * RR * DD], g_Xl[BB * RR * DD];
__device__ h16   g_Yh[BB * TT * DD], g_Yl[BB * TT * DD];
__device__ h16   g_Wrh[DD * HH], g_Wrl[DD * HH];
__device__ h16   g_Wqh[DD * HH], g_Wql[DD * HH];
__device__ h16   g_Mh[DD * DD], g_Ml[DD * DD];
__device__ h16   g_W2h[BB * 2 * TT * DD], g_W2l[BB * 2 * TT * DD];
__device__ float g_Mscr[4 * DD * DD];         // 16 MB: M split-K partials
__device__ float g_c[BB * TT], g_z[BB * TT], g_base[BB * RR];
__device__ float g_wc[DD];

// ---------------- fork/join resources (host-side, created pre-main) ---------
struct HostRes {
    cudaStream_t sB, sC, sD;
    cudaEvent_t evRoot, evY, evX, evVa, evSa, evG;
    HostRes() {
        int lo = 0, hi = 0;
        cudaDeviceGetStreamPriorityRange(&lo, &hi);   // lo = least priority
        cudaStreamCreateWithFlags(&sB, cudaStreamNonBlocking);
        cudaStreamCreateWithPriority(&sC, cudaStreamNonBlocking, lo);  // G backfill
        cudaStreamCreateWithFlags(&sD, cudaStreamNonBlocking);
        cudaEventCreateWithFlags(&evRoot, cudaEventDisableTiming);
        cudaEventCreateWithFlags(&evY,  cudaEventDisableTiming);
        cudaEventCreateWithFlags(&evX,  cudaEventDisableTiming);
        cudaEventCreateWithFlags(&evVa, cudaEventDisableTiming);
        cudaEventCreateWithFlags(&evSa, cudaEventDisableTiming);
        cudaEventCreateWithFlags(&evG,  cudaEventDisableTiming);
    }
};
static HostRes g_res;

// ---------------- helpers ---------------------------------------------------
__device__ __forceinline__ uint32_t smem_u32(const void* p) {
    return (uint32_t)__cvta_generic_to_shared(p);
}
__device__ __forceinline__ void cp16(void* s, const void* g) {
    asm volatile("cp.async.ca.shared.global [%0], [%1], 16;\n"
                 :: "r"(smem_u32(s)), "l"(g));
}
__device__ __forceinline__ void cp_commit() { asm volatile("cp.async.commit_group;\n"); }
template <int N>
__device__ __forceinline__ void cp_wait() { asm volatile("cp.async.wait_group %0;\n" :: "n"(N)); }

__device__ __forceinline__ void ldm_x4(uint32_t* r, uint32_t addr) {
    asm volatile("ldmatrix.sync.aligned.m8n8.x4.shared.b16 {%0,%1,%2,%3}, [%4];"
                 : "=r"(r[0]), "=r"(r[1]), "=r"(r[2]), "=r"(r[3]) : "r"(addr));
}
__device__ __forceinline__ void mma16816(float* d, const uint32_t* a, const uint32_t* b) {
    asm volatile(
        "mma.sync.aligned.m16n8k16.row.col.f32.f16.f16.f32 "
        "{%0,%1,%2,%3},{%4,%5,%6,%7},{%8,%9},{%0,%1,%2,%3};"
        : "+f"(d[0]), "+f"(d[1]), "+f"(d[2]), "+f"(d[3])
        : "r"(a[0]), "r"(a[1]), "r"(a[2]), "r"(a[3]), "r"(b[0]), "r"(b[1]));
}

__device__ __forceinline__ void split1(float v, h16& h, h16& l) {
    h = __float2half_rn(v);
    l = __float2half_rn(v - __half2float(h));
}
__device__ __forceinline__ uint32_t pk2(h16 a, h16 b) {
    return (uint32_t)__half_as_ushort(a) | ((uint32_t)__half_as_ushort(b) << 16);
}

// ---------------- split / fused prep kernels ---------------------------------
__global__ __launch_bounds__(256) void split_kernel(
    const float4* __restrict__ in, uint2* __restrict__ h, uint2* __restrict__ l)
{
    int i = blockIdx.x * 256 + threadIdx.x;
    float4 v = in[i];
    h16 h0, l0, h1, l1, h2, l2, h3, l3;
    split1(v.x, h0, l0); split1(v.y, h1, l1); split1(v.z, h2, l2); split1(v.w, h3, l3);
    h[i] = make_uint2(pk2(h0, h1), pk2(h2, h3));
    l[i] = make_uint2(pk2(l0, l1), pk2(l2, l3));
}

// X prep: one block per row. Split X -> Xh/Xl and base[row] = X·Ws1 + bs.
__global__ __launch_bounds__(256) void xprep_kernel(
    const float4* __restrict__ X, const float4* __restrict__ ws1,
    const float* __restrict__ bs,
    uint2* __restrict__ Xh, uint2* __restrict__ Xl, float* __restrict__ base)
{
    const int row = blockIdx.x, t = threadIdx.x;
    const int i = row * 256 + t;
    float4 v = X[i];
    h16 h0, l0, h1, l1, h2, l2, h3, l3;
    split1(v.x, h0, l0); split1(v.y, h1, l1); split1(v.z, h2, l2); split1(v.w, h3, l3);
    Xh[i] = make_uint2(pk2(h0, h1), pk2(h2, h3));
    Xl[i] = make_uint2(pk2(l0, l1), pk2(l2, l3));

    float4 w = ws1[t];
    float s = v.x * w.x + v.y * w.y + v.z * w.z + v.w * w.w;
    __shared__ float red[8];
    #pragma unroll
    for (int o = 16; o; o >>= 1) s += __shfl_xor_sync(0xffffffffu, s, o);
    if ((t & 31) == 0) red[t >> 5] = s;
    __syncthreads();
    if (t == 0) {
        float r = 0.f;
        #pragma unroll
        for (int k = 0; k < 8; k++) r += red[k];
        base[row] = r + bs[0];
    }
}

// Y prep: one block per (b,t) row. Split Y -> Yh/Yl; fp16(Y*ws3) -> W2 bottom row
// (high limb only — G GEMM is 1-phase); c[row] = Y·wc; z[row] = Y·Ws2.
__global__ __launch_bounds__(256) void yprep_kernel(
    const float4* __restrict__ Y, const float4* __restrict__ Ws,
    const float4* __restrict__ wc,
    uint2* __restrict__ Yh, uint2* __restrict__ Yl,
    uint2* __restrict__ W2h,
    float* __restrict__ cb, float* __restrict__ zb)
{
    const int row = blockIdx.x, t = threadIdx.x;     // row in [0, 8192)
    const int b = row >> 9, tt = row & 511;
    const int i = row * 256 + t;
    float4 v = Y[i];
    h16 h0, l0, h1, l1, h2, l2, h3, l3;
    split1(v.x, h0, l0); split1(v.y, h1, l1); split1(v.z, h2, l2); split1(v.w, h3, l3);
    Yh[i] = make_uint2(pk2(h0, h1), pk2(h2, h3));
    Yl[i] = make_uint2(pk2(l0, l1), pk2(l2, l3));

    float4 w3 = Ws[512 + t];                          // ws3 = Ws + 2048 floats
    h16 g0 = __float2half_rn(v.x * w3.x), g1 = __float2half_rn(v.y * w3.y);
    h16 g2 = __float2half_rn(v.z * w3.z), g3 = __float2half_rn(v.w * w3.w);
    const int o = (b * 1024 + 512 + tt) * 256 + t;    // W2 bottom row, uint2 units
    W2h[o] = make_uint2(pk2(g0, g1), pk2(g2, g3));

    float4 u = wc[t];
    float4 w2 = Ws[256 + t];                          // ws2 = Ws + 1024 floats
    float s1 = v.x * u.x + v.y * u.y + v.z * u.z + v.w * u.w;
    float s2 = v.x * w2.x + v.y * w2.y + v.z * w2.z + v.w * w2.w;
    __shared__ float r1[8], r2[8];
    #pragma unroll
    for (int o2 = 16; o2; o2 >>= 1) {
        s1 += __shfl_xor_sync(0xffffffffu, s1, o2);
        s2 += __shfl_xor_sync(0xffffffffu, s2, o2);
    }
    if ((t & 31) == 0) { r1[t >> 5] = s1; r2[t >> 5] = s2; }
    __syncthreads();
    if (t == 0) {
        float a1 = 0.f, a2 = 0.f;
        #pragma unroll
        for (int k = 0; k < 8; k++) { a1 += r1[k]; a2 += r2[k]; }
        cb[row] = a1; zb[row] = a2;
    }
}

// reduce 4 split-K fp32 partials of M and split to h/l
__global__ __launch_bounds__(256) void reduce_split_kernel(
    const float4* __restrict__ part, uint2* __restrict__ h, uint2* __restrict__ l)
{
    int i = blockIdx.x * 256 + threadIdx.x;
    const int S = DD * DD / 4;
    float4 a = part[i], b = part[i + S], c = part[i + 2 * S], d = part[i + 3 * S];
    float4 v = make_float4(a.x + b.x + c.x + d.x, a.y + b.y + c.y + d.y,
                           a.z + b.z + c.z + d.z, a.w + b.w + c.w + d.w);
    h16 h0, l0, h1, l1, h2, l2, h3, l3;
    split1(v.x, h0, l0); split1(v.y, h1, l1); split1(v.z, h2, l2); split1(v.w, h3, l3);
    h[i] = make_uint2(pk2(h0, h1), pk2(h2, h3));
    l[i] = make_uint2(pk2(l0, l1), pk2(l2, l3));
}

// ---------------- fp16 split NT GEMM (R3/R8-proven inner loop) ---------------
// C[m,n] = sum over NPH phases: (0) Ah*Bh, (1) Al*Bh, (2) Ah*Bl. K per phase, row stride ld.
// EPI=0: fp32 store to C. EPI=1: split-store h16 into Ch/Cl. EPI=2: fp16 store to Ch.
template <int EPI, int NPH>
__global__ __launch_bounds__(256, 2) void gemm_h16_nt(
    const h16* __restrict__ Ah, const h16* __restrict__ Al,
    const h16* __restrict__ Bh, const h16* __restrict__ Bl,
    float* __restrict__ C, h16* __restrict__ Ch, h16* __restrict__ Cl,
    int K, int ld, int ldc, long long sA, long long sB, long long sC)
{
    const int bz = blockIdx.z;
    Ah += bz * sA; Al += bz * sA; Bh += bz * sB; Bl += bz * sB;

    const int m0 = blockIdx.y * 128, n0 = blockIdx.x * 128;
    const int tid = threadIdx.x, lane = tid & 31, wid = tid >> 5;
    const int wm = (wid & 1) * 64, wn = (wid >> 1) * 32;

    __shared__ h16 sm[2][2][128 * 40];

    float acc[4][4][4];
    #pragma unroll
    for (int i = 0; i < 4; i++)
        #pragma unroll
        for (int j = 0; j < 4; j++)
            #pragma unroll
            for (int q = 0; q < 4; q++) acc[i][j][q] = 0.f;

    const int ar0 = tid >> 2,          ak0 = (tid & 3) * 8;
    const int ar1 = (tid + 256) >> 2,  ak1 = ((tid + 256) & 3) * 8;

    const int nch = (NPH * K) / 32;

    auto issue = [&](int chunk, int stage) {
        int kk = chunk * 32;
        int phase = kk / K, kin = kk - phase * K;
        const h16* pA = (phase == 1) ? Al : Ah;
        const h16* pB = (phase == 2) ? Bl : Bh;
        cp16(&sm[stage][0][ar0 * 40 + ak0], pA + (long long)(m0 + ar0) * ld + kin + ak0);
        cp16(&sm[stage][0][ar1 * 40 + ak1], pA + (long long)(m0 + ar1) * ld + kin + ak1);
        cp16(&sm[stage][1][ar0 * 40 + ak0], pB + (long long)(n0 + ar0) * ld + kin + ak0);
        cp16(&sm[stage][1][ar1 * 40 + ak1], pB + (long long)(n0 + ar1) * ld + kin + ak1);
        cp_commit();
    };

    issue(0, 0);

    const int aRow = lane & 15, aKof = (lane >> 4) * 8;
    const int bRow = ((lane >> 4) << 3) + (lane & 7), bKof = ((lane >> 3) & 1) * 8;

    for (int c = 0; c < nch; c++) {
        int st = c & 1;
        if (c + 1 < nch) { issue(c + 1, st ^ 1); cp_wait<1>(); }
        else             { cp_wait<0>(); }
        __syncthreads();

        #pragma unroll
        for (int ks = 0; ks < 32; ks += 16) {
            uint32_t af[4][4];
            #pragma unroll
            for (int mt = 0; mt < 4; mt++)
                ldm_x4(af[mt], smem_u32(&sm[st][0][(wm + mt * 16 + aRow) * 40 + ks + aKof]));
            uint32_t bfr[2][4];
            #pragma unroll
            for (int bt = 0; bt < 2; bt++)
                ldm_x4(bfr[bt], smem_u32(&sm[st][1][(wn + bt * 16 + bRow) * 40 + ks + bKof]));
            #pragma unroll
            for (int mt = 0; mt < 4; mt++) {
                #pragma unroll
                for (int nt = 0; nt < 4; nt++) {
                    mma16816(acc[mt][nt], af[mt], &bfr[nt >> 1][(nt & 1) * 2]);
                }
            }
        }
        __syncthreads();
    }

    // epilogue
    const int tg = lane >> 2, tl = lane & 3;
    #pragma unroll
    for (int mt = 0; mt < 4; mt++) {
        #pragma unroll
        for (int nt = 0; nt < 4; nt++) {
            int m = m0 + wm + mt * 16 + tg;
            int n = n0 + wn + nt * 8 + 2 * tl;
            float v0 = acc[mt][nt][0], v1 = acc[mt][nt][1];
            float v2 = acc[mt][nt][2], v3 = acc[mt][nt][3];
            if (EPI == 0) {
                float* Cb = C + bz * sC;
                *reinterpret_cast<float2*>(&Cb[(long long)m * ldc + n])       = make_float2(v0, v1);
                *reinterpret_cast<float2*>(&Cb[(long long)(m + 8) * ldc + n]) = make_float2(v2, v3);
            } else if (EPI == 1) {
                h16 h0,l0,h1,l1,h2,l2,h3,l3;
                split1(v0, h0, l0); split1(v1, h1, l1); split1(v2, h2, l2); split1(v3, h3, l3);
                h16* Hb = Ch + bz * sC; h16* Lb = Cl + bz * sC;
                *reinterpret_cast<uint32_t*>(&Hb[(long long)m * ldc + n])       = pk2(h0, h1);
                *reinterpret_cast<uint32_t*>(&Lb[(long long)m * ldc + n])       = pk2(l0, l1);
                *reinterpret_cast<uint32_t*>(&Hb[(long long)(m + 8) * ldc + n]) = pk2(h2, h3);
                *reinterpret_cast<uint32_t*>(&Lb[(long long)(m + 8) * ldc + n]) = pk2(l2, l3);
            } else {
                h16* Gb = Ch + bz * sC;
                *reinterpret_cast<uint32_t*>(&Gb[(long long)m * ldc + n]) =
                    pk2(__float2half_rn(v0), __float2half_rn(v1));
                *reinterpret_cast<uint32_t*>(&Gb[(long long)(m + 8) * ldc + n]) =
                    pk2(__float2half_rn(v2), __float2half_rn(v3));
            }
        }
    }
}

// ---------------- aux kernels (fp32) ----------------------------------------
__global__ __launch_bounds__(256) void rowdot_kernel(
    const float* __restrict__ A, const float* __restrict__ v,
    const float* __restrict__ addp, float* __restrict__ out, int K)
{
    int row = blockIdx.x * 8 + (threadIdx.x >> 5);
    int lane = threadIdx.x & 31;
    const float* a = A + (long long)row * K;
    float s = 0.f;
    for (int i = lane * 4; i < K; i += 128) {
        float4 x = *reinterpret_cast<const float4*>(&a[i]);
        float4 w = *reinterpret_cast<const float4*>(&v[i]);
        s += x.x * w.x + x.y * w.y + x.z * w.z + x.w * w.w;
    }
    #pragma unroll
    for (int o = 16; o; o >>= 1) s += __shfl_xor_sync(0xffffffffu, s, o);
    if (lane == 0) out[row] = s + (addp ? addp[0] : 0.f);
}

__global__ __launch_bounds__(256) void softmax_out_kernel(
    const float* __restrict__ S, const h16* __restrict__ G,
    const float* __restrict__ c, const float* __restrict__ z,
    const float* __restrict__ base, float* __restrict__ out)
{
    const int b = blockIdx.y, r = blockIdx.x;
    const float* Srow = S + ((long long)b * RR + r) * TT;
    const h16*   Grow = G + ((long long)b * RR + r) * TT;
    const float* cbp = c + b * TT;
    const float* zbp = z + b * TT;
    const int t = threadIdx.x;
    const int lane = t & 31, wid = t >> 5;

    float s0 = Srow[t]       + cbp[t];
    float s1 = Srow[t + 256] + cbp[t + 256];
    float g0 = __half2float(Grow[t]);
    float g1 = __half2float(Grow[t + 256]);

    __shared__ float sm[8], smp[8], smw[8];

    float m = fmaxf(s0, s1);
    #pragma unroll
    for (int o = 16; o; o >>= 1) m = fmaxf(m, __shfl_xor_sync(0xffffffffu, m, o));
    if (lane == 0) sm[wid] = m;
    __syncthreads();
    if (wid == 0) {
        float v = sm[lane & 7];
        #pragma unroll
        for (int o = 4; o; o >>= 1) v = fmaxf(v, __shfl_xor_sync(0xffffffffu, v, o));
        if (lane == 0) sm[0] = v;
    }
    __syncthreads();
    m = sm[0];

    float p0 = expf(s0 - m), p1 = expf(s1 - m);
    float ps = p0 + p1;
    float ws = p0 * (zbp[t] + g0) + p1 * (zbp[t + 256] + g1);
    #pragma unroll
    for (int o = 16; o; o >>= 1) {
        ps += __shfl_xor_sync(0xffffffffu, ps, o);
        ws += __shfl_xor_sync(0xffffffffu, ws, o);
    }
    if (lane == 0) { smp[wid] = ps; smw[wid] = ws; }
    __syncthreads();
    if (t == 0) {
        float tp = 0.f, tw = 0.f;
        #pragma unroll
        for (int i = 0; i < 8; i++) { tp += smp[i]; tw += smw[i]; }
        out[b * RR + r] = base[b * RR + r] + tw / tp;
    }
}

// ---------------- launch ----------------------------------------------------
extern "C" void kernel_launch(void* const* d_in, const int* in_sizes, int n_in,
                              void* d_out, int out_size)
{
    const float* X  = (const float*)d_in[0]; // [B,R,D]
    const float* Y  = (const float*)d_in[1]; // [B,T,D]
    const float* Wr = (const float*)d_in[2]; // [D,H]
    const float* br = (const float*)d_in[3]; // [H]
    const float* Wq = (const float*)d_in[4]; // [D,H]
    const float* bq = (const float*)d_in[5]; // [H] (enters only via softmax-invariant terms)
    const float* Ws = (const float*)d_in[6]; // [3D]
    const float* bs = (const float*)d_in[7]; // [1]
    float* out = (float*)d_out;
    (void)bq;

    float *P, *Mscr, *cb, *zb, *baseb, *wc;
    h16 *G, *Xh, *Xl, *Yh, *Yl, *Wrh, *Wrl, *Wqh, *Wql, *Mh, *Ml, *W2h, *W2l;
    cudaGetSymbolAddress((void**)&P, g_P);
    cudaGetSymbolAddress((void**)&G, g_G);
    cudaGetSymbolAddress((void**)&Mscr, g_Mscr);
    cudaGetSymbolAddress((void**)&cb, g_c);
    cudaGetSymbolAddress((void**)&zb, g_z);
    cudaGetSymbolAddress((void**)&baseb, g_base);
    cudaGetSymbolAddress((void**)&wc, g_wc);
    cudaGetSymbolAddress((void**)&Xh, g_Xh);   cudaGetSymbolAddress((void**)&Xl, g_Xl);
    cudaGetSymbolAddress((void**)&Yh, g_Yh);   cudaGetSymbolAddress((void**)&Yl, g_Yl);
    cudaGetSymbolAddress((void**)&Wrh, g_Wrh); cudaGetSymbolAddress((void**)&Wrl, g_Wrl);
    cudaGetSymbolAddress((void**)&Wqh, g_Wqh); cudaGetSymbolAddress((void**)&Wql, g_Wql);
    cudaGetSymbolAddress((void**)&Mh, g_Mh);   cudaGetSymbolAddress((void**)&Ml, g_Ml);
    cudaGetSymbolAddress((void**)&W2h, g_W2h); cudaGetSymbolAddress((void**)&W2l, g_W2l);

    cudaStream_t sB = g_res.sB, sC = g_res.sC, sD = g_res.sD;

    // ---- fork side streams from the (possibly capturing) main stream ----
    cudaEventRecord(g_res.evRoot, 0);
    cudaStreamWaitEvent(sB, g_res.evRoot, 0);

    // ---- sB: wc -> yprep [evY] -> xprep [evX] ----
    rowdot_kernel<<<DD / 8, 256, 0, sB>>>(Wq, br, nullptr, wc, HH);
    yprep_kernel<<<BB * TT, 256, 0, sB>>>((const float4*)Y, (const float4*)Ws, (const float4*)wc,
                                          (uint2*)Yh, (uint2*)Yl, (uint2*)W2h, cb, zb);
    cudaEventRecord(g_res.evY, sB);
    xprep_kernel<<<BB * RR, 256, 0, sB>>>((const float4*)X, (const float4*)Ws, bs,
                                          (uint2*)Xh, (uint2*)Xl, baseb);
    cudaEventRecord(g_res.evX, sB);

    // ---- sC (lowest priority): G = X @ Yw^T (fp16, 1-phase) — pure backfill ----
    cudaStreamWaitEvent(sC, g_res.evX, 0);
    gemm_h16_nt<2, 1><<<dim3(4, 8, BB), 256, 0, sC>>>(
        Xh, nullptr, W2h + (long long)512 * DD, nullptr, nullptr, G, nullptr,
        DD, DD, TT, (long long)RR * DD, (long long)2 * TT * DD, (long long)RR * TT);
    cudaEventRecord(g_res.evG, sC);

    // ---- main: weight splits -> M -> reduce ----
    split_kernel<<<DD * HH / 1024, 256>>>((const float4*)Wr, (uint2*)Wrh, (uint2*)Wrl);
    split_kernel<<<DD * HH / 1024, 256>>>((const float4*)Wq, (uint2*)Wqh, (uint2*)Wql);
    gemm_h16_nt<0, 3><<<dim3(8, 8, 4), 256>>>(
        Wrh, Wrl, Wqh, Wql, Mscr, nullptr, nullptr,
        256, HH, DD, 256LL, 256LL, (long long)DD * DD);
    reduce_split_kernel<<<DD * DD / 1024, 256>>>((const float4*)Mscr, (uint2*)Mh, (uint2*)Ml);

    // ---- V split by t-rows: V_a = rows [0,256), V_b = rows [256,512) ----
    cudaStreamWaitEvent(0, g_res.evY, 0);
    // V_a: W2 rows 0..255 (all batches)
    gemm_h16_nt<1, 3><<<dim3(8, 2, BB), 256>>>(
        Yh, Yl, Mh, Ml, nullptr, W2h, W2l,
        DD, DD, DD, (long long)TT * DD, 0LL, (long long)2 * TT * DD);
    cudaEventRecord(g_res.evVa, 0);
    // V_b: W2 rows 256..511 (A rows and C rows offset by 256)
    gemm_h16_nt<1, 3><<<dim3(8, 2, BB), 256>>>(
        Yh + (long long)256 * DD, Yl + (long long)256 * DD, Mh, Ml,
        nullptr, W2h + (long long)256 * DD, W2l + (long long)256 * DD,
        DD, DD, DD, (long long)TT * DD, 0LL, (long long)2 * TT * DD);

    // ---- sD: S_a = X @ V^T cols [0,256) — overlaps V_b ----
    cudaStreamWaitEvent(sD, g_res.evVa, 0);
    cudaStreamWaitEvent(sD, g_res.evX, 0);
    gemm_h16_nt<0, 3><<<dim3(2, 8, BB), 256, 0, sD>>>(
        Xh, Xl, W2h, W2l, P, nullptr, nullptr,
        DD, DD, TT, (long long)RR * DD, (long long)2 * TT * DD, (long long)RR * TT);
    cudaEventRecord(g_res.evSa, sD);

    // ---- main: S_b = cols [256,512) (after V_b, same stream) ----
    cudaStreamWaitEvent(0, g_res.evX, 0);
    gemm_h16_nt<0, 3><<<dim3(2, 8, BB), 256>>>(
        Xh, Xl, W2h + (long long)256 * DD, W2l + (long long)256 * DD, P + 256,
        nullptr, nullptr,
        DD, DD, TT, (long long)RR * DD, (long long)2 * TT * DD, (long long)RR * TT);

    // ---- join everything, then softmax + fused epilogue ----
    cudaStreamWaitEvent(0, g_res.evSa, 0);
    cudaStreamWaitEvent(0, g_res.evG, 0);
    softmax_out_kernel<<<dim3(RR, BB), 256>>>(P, G, cb, zb, baseb, out);
}